// round 2
// baseline (speedup 1.0000x reference)
#include <cuda_runtime.h>
#include <cstdint>

// Problem constants (fixed by the reference)
#define NN 1024
#define SS 64
#define DD 256
#define HH 4
#define HDIM 64
#define EE 4096
#define MROWS (NN * SS)   // 65536

// ---------------- scratch (device globals; no allocs allowed) ----------------
__device__ float g_xn[MROWS * DD];    // layernormed features
__device__ float g_q[MROWS * DD];
__device__ float g_k[MROWS * DD];
__device__ float g_v[MROWS * DD];
__device__ float g_ctx[MROWS * DD];   // per-src summed context (pre out-proj)
__device__ int g_deg[NN];
__device__ int g_off[NN + 1];
__device__ int g_adj[EE];             // dst ids grouped by src, deterministic order
__device__ int g_step;                // 1 if edge_index is int32, 2 if int64

// ---------------- edge dtype detection ----------------
// If edge_index is int64, node ids (< 1024, nonneg) have zero high words, so
// every odd 32-bit word of the src row is 0. If int32, odd words are other
// node ids (nonzero with overwhelming probability over 4096 samples).
__global__ void detect_kernel(const int* __restrict__ ei32) {
    int nz = 0;
    for (int i = threadIdx.x; i < EE; i += blockDim.x)
        nz |= (ei32[2 * i + 1] != 0);
    nz = __syncthreads_or(nz);
    if (threadIdx.x == 0) g_step = nz ? 1 : 2;
}

__device__ __forceinline__ int edge_val(const int* __restrict__ ei32, int row, int e) {
    return ei32[g_step * (row * EE + e)];
}

// ---------------- LayerNorm: one warp per row of 256 ----------------
__global__ __launch_bounds__(256) void ln_kernel(const float* __restrict__ x,
                                                 const float* __restrict__ w,
                                                 const float* __restrict__ b) {
    int warp = (blockIdx.x * blockDim.x + threadIdx.x) >> 5;
    int lane = threadIdx.x & 31;
    if (warp >= MROWS) return;
    const float* xr = x + (size_t)warp * DD + lane * 8;
    float4 a = *(const float4*)xr;
    float4 c = *(const float4*)(xr + 4);
    float s  = a.x + a.y + a.z + a.w + c.x + c.y + c.z + c.w;
    float s2 = a.x*a.x + a.y*a.y + a.z*a.z + a.w*a.w
             + c.x*c.x + c.y*c.y + c.z*c.z + c.w*c.w;
    #pragma unroll
    for (int o = 16; o > 0; o >>= 1) {
        s  += __shfl_xor_sync(0xffffffffu, s,  o);
        s2 += __shfl_xor_sync(0xffffffffu, s2, o);
    }
    float mu  = s * (1.0f / DD);
    float var = s2 * (1.0f / DD) - mu * mu;
    float r = rsqrtf(var + 1e-5f);
    float4 w0 = *(const float4*)(w + lane * 8);
    float4 w1 = *(const float4*)(w + lane * 8 + 4);
    float4 b0 = *(const float4*)(b + lane * 8);
    float4 b1 = *(const float4*)(b + lane * 8 + 4);
    float* o = g_xn + (size_t)warp * DD + lane * 8;
    float4 o0, o1;
    o0.x = (a.x - mu) * r * w0.x + b0.x;  o0.y = (a.y - mu) * r * w0.y + b0.y;
    o0.z = (a.z - mu) * r * w0.z + b0.z;  o0.w = (a.w - mu) * r * w0.w + b0.w;
    o1.x = (c.x - mu) * r * w1.x + b1.x;  o1.y = (c.y - mu) * r * w1.y + b1.y;
    o1.z = (c.z - mu) * r * w1.z + b1.z;  o1.w = (c.w - mu) * r * w1.w + b1.w;
    *(float4*)o = o0;
    *(float4*)(o + 4) = o1;
}

// ---------------- CSR build (deterministic edge order per src) ----------------
__global__ void csr_zero() { if (threadIdx.x < NN) g_deg[threadIdx.x] = 0; }

__global__ void csr_hist(const int* __restrict__ ei32) {
    int e = blockIdx.x * blockDim.x + threadIdx.x;
    if (e < EE) atomicAdd(&g_deg[edge_val(ei32, 0, e)], 1);
}

__global__ void csr_scan() {  // one block, NN threads, Hillis-Steele inclusive
    __shared__ int s[NN];
    int t = threadIdx.x;
    s[t] = g_deg[t];
    __syncthreads();
    for (int o = 1; o < NN; o <<= 1) {
        int v = (t >= o) ? s[t - o] : 0;
        __syncthreads();
        s[t] += v;
        __syncthreads();
    }
    g_off[t + 1] = s[t];
    if (t == 0) g_off[0] = 0;
}

__global__ void csr_scatter(const int* __restrict__ ei32) {
    int e = blockIdx.x * blockDim.x + threadIdx.x;
    if (e >= EE) return;
    int src = edge_val(ei32, 0, e);
    int cnt = 0;  // rank among earlier edges with same src -> deterministic
    for (int j = 0; j < e; j++) cnt += (edge_val(ei32, 0, j) == src);
    g_adj[g_off[src] + cnt] = edge_val(ei32, 1, e);
}

// ---------------- SGEMM: C[M,256] = A[M,256] @ W[256,256] + bias ----------------
// Optional fused epilogue: out = (C + resid) * mask[row]
__global__ __launch_bounds__(256) void gemm_kernel(const float* __restrict__ A,
                                                   const float* __restrict__ W,
                                                   const float* __restrict__ bias,
                                                   float* __restrict__ C,
                                                   const float* __restrict__ resid,
                                                   const float* __restrict__ mask) {
    __shared__ __align__(16) float As[16 * 132];  // [k][m], m-stride 132
    __shared__ __align__(16) float Bs[16 * 64];   // [k][n]
    int tid = threadIdx.x;
    int tx = tid & 15, ty = tid >> 4;
    int m0 = blockIdx.y * 128, n0 = blockIdx.x * 64;
    float acc[8][4];
    #pragma unroll
    for (int i = 0; i < 8; i++)
        #pragma unroll
        for (int j = 0; j < 4; j++) acc[i][j] = 0.0f;

    for (int k0 = 0; k0 < DD; k0 += 16) {
        #pragma unroll
        for (int it = 0; it < 2; it++) {
            int f4 = tid * 2 + it;
            int r = f4 >> 2, c4 = f4 & 3;
            float4 av = *(const float4*)(A + (size_t)(m0 + r) * DD + k0 + c4 * 4);
            int kb = c4 * 4;
            As[(kb + 0) * 132 + r] = av.x;
            As[(kb + 1) * 132 + r] = av.y;
            As[(kb + 2) * 132 + r] = av.z;
            As[(kb + 3) * 132 + r] = av.w;
        }
        {
            int r = tid >> 4, c = (tid & 15) * 4;
            *(float4*)&Bs[r * 64 + c] = *(const float4*)(W + (size_t)(k0 + r) * DD + n0 + c);
        }
        __syncthreads();
        #pragma unroll
        for (int kk = 0; kk < 16; kk++) {
            float4 a0 = *(float4*)&As[kk * 132 + ty * 8];
            float4 a1 = *(float4*)&As[kk * 132 + ty * 8 + 4];
            float4 bv = *(float4*)&Bs[kk * 64 + tx * 4];
            float aa[8] = {a0.x, a0.y, a0.z, a0.w, a1.x, a1.y, a1.z, a1.w};
            #pragma unroll
            for (int i = 0; i < 8; i++) {
                acc[i][0] = fmaf(aa[i], bv.x, acc[i][0]);
                acc[i][1] = fmaf(aa[i], bv.y, acc[i][1]);
                acc[i][2] = fmaf(aa[i], bv.z, acc[i][2]);
                acc[i][3] = fmaf(aa[i], bv.w, acc[i][3]);
            }
        }
        __syncthreads();
    }
    float4 bb = *(const float4*)(bias + n0 + tx * 4);
    #pragma unroll
    for (int i = 0; i < 8; i++) {
        int m = m0 + ty * 8 + i;
        float vx = acc[i][0] + bb.x;
        float vy = acc[i][1] + bb.y;
        float vz = acc[i][2] + bb.z;
        float vw = acc[i][3] + bb.w;
        if (resid) {
            float4 rv = *(const float4*)(resid + (size_t)m * DD + n0 + tx * 4);
            float mk = mask[m];
            vx = (vx + rv.x) * mk;  vy = (vy + rv.y) * mk;
            vz = (vz + rv.z) * mk;  vw = (vw + rv.w) * mk;
        }
        *(float4*)(C + (size_t)m * DD + n0 + tx * 4) = make_float4(vx, vy, vz, vw);
    }
}

// ---------------- per-(src,head) edge attention ----------------
// CTA = (src, head). Iterates incident edges; accumulates ctx in registers.
// The per-edge scalar bias is constant along the softmax axis, so it cancels.
__global__ __launch_bounds__(128) void attn_kernel(const float* __restrict__ masks) {
    extern __shared__ __align__(16) float sm[];
    float* Qs  = sm;            // 64 x (stride 68)
    float* Ks  = sm + 4352;
    float* Vs  = sm + 8704;
    float* Sc  = sm + 13056;    // 64 x (stride 65) attention probs
    float* kmS = sm + 17216;    // 64 key masks

    int src = blockIdx.x >> 2;
    int h   = blockIdx.x & 3;
    int tid = threadIdx.x;
    int qg = tid >> 3;          // 16 groups of 4 q-rows
    int kg = tid & 7;           // 8 groups (k = j*8+kg / d = kg*8+j)

    {   // load Q tile [64 x 64] for this head
        int r = tid >> 1, cb = (tid & 1) * 32;
        const float* gq = g_q + ((size_t)src * SS + r) * DD + h * HDIM;
        #pragma unroll
        for (int c = 0; c < 8; c++)
            *(float4*)&Qs[r * 68 + cb + c * 4] = *(const float4*)(gq + cb + c * 4);
    }
    float acc[4][8];
    #pragma unroll
    for (int i = 0; i < 4; i++)
        #pragma unroll
        for (int j = 0; j < 8; j++) acc[i][j] = 0.0f;

    int e0 = g_off[src], e1 = g_off[src + 1];
    __syncthreads();

    for (int e = e0; e < e1; e++) {
        int dst = g_adj[e];
        {   // load K, V tiles + key mask
            int r = tid >> 1, cb = (tid & 1) * 32;
            const float* gk = g_k + ((size_t)dst * SS + r) * DD + h * HDIM;
            const float* gv = g_v + ((size_t)dst * SS + r) * DD + h * HDIM;
            #pragma unroll
            for (int c = 0; c < 8; c++) {
                *(float4*)&Ks[r * 68 + cb + c * 4] = *(const float4*)(gk + cb + c * 4);
                *(float4*)&Vs[r * 68 + cb + c * 4] = *(const float4*)(gv + cb + c * 4);
            }
            if (tid < SS) kmS[tid] = masks[dst * SS + tid];
        }
        __syncthreads();

        // ---- scores: thread block of 4 q x 8 k ----
        float sc[4][8];
        #pragma unroll
        for (int i = 0; i < 4; i++)
            #pragma unroll
            for (int j = 0; j < 8; j++) sc[i][j] = 0.0f;
        #pragma unroll
        for (int d = 0; d < 64; d += 4) {
            float4 qv[4], kv[8];
            #pragma unroll
            for (int i = 0; i < 4; i++) qv[i] = *(float4*)&Qs[(qg * 4 + i) * 68 + d];
            #pragma unroll
            for (int j = 0; j < 8; j++) kv[j] = *(float4*)&Ks[(j * 8 + kg) * 68 + d];
            #pragma unroll
            for (int i = 0; i < 4; i++)
                #pragma unroll
                for (int j = 0; j < 8; j++) {
                    sc[i][j] = fmaf(qv[i].x, kv[j].x, sc[i][j]);
                    sc[i][j] = fmaf(qv[i].y, kv[j].y, sc[i][j]);
                    sc[i][j] = fmaf(qv[i].z, kv[j].z, sc[i][j]);
                    sc[i][j] = fmaf(qv[i].w, kv[j].w, sc[i][j]);
                }
        }
        // ---- scale, mask, softmax over k (8 lanes per q-row share via shfl) ----
        float mx[4] = {-1e30f, -1e30f, -1e30f, -1e30f};
        #pragma unroll
        for (int i = 0; i < 4; i++)
            #pragma unroll
            for (int j = 0; j < 8; j++) {
                float km = kmS[j * 8 + kg];
                float s = (km > 0.0f) ? sc[i][j] * 0.125f : -1e30f;
                sc[i][j] = s;
                mx[i] = fmaxf(mx[i], s);
            }
        #pragma unroll
        for (int i = 0; i < 4; i++) {
            mx[i] = fmaxf(mx[i], __shfl_xor_sync(0xffffffffu, mx[i], 1));
            mx[i] = fmaxf(mx[i], __shfl_xor_sync(0xffffffffu, mx[i], 2));
            mx[i] = fmaxf(mx[i], __shfl_xor_sync(0xffffffffu, mx[i], 4));
        }
        float sum[4] = {0.0f, 0.0f, 0.0f, 0.0f};
        #pragma unroll
        for (int i = 0; i < 4; i++)
            #pragma unroll
            for (int j = 0; j < 8; j++) {
                float p = __expf(sc[i][j] - mx[i]) * kmS[j * 8 + kg];
                sc[i][j] = p;
                sum[i] += p;
            }
        #pragma unroll
        for (int i = 0; i < 4; i++) {
            sum[i] += __shfl_xor_sync(0xffffffffu, sum[i], 1);
            sum[i] += __shfl_xor_sync(0xffffffffu, sum[i], 2);
            sum[i] += __shfl_xor_sync(0xffffffffu, sum[i], 4);
            float inv = (sum[i] > 0.0f) ? (1.0f / sum[i]) : 0.0f;
            #pragma unroll
            for (int j = 0; j < 8; j++)
                Sc[(qg * 4 + i) * 65 + j * 8 + kg] = sc[i][j] * inv;
        }
        __syncthreads();

        // ---- ctx += attn @ V : thread block of 4 q x 8 d (d = kg*8+j) ----
        #pragma unroll 8
        for (int k = 0; k < 64; k++) {
            float a0 = Sc[(qg * 4 + 0) * 65 + k];
            float a1 = Sc[(qg * 4 + 1) * 65 + k];
            float a2 = Sc[(qg * 4 + 2) * 65 + k];
            float a3 = Sc[(qg * 4 + 3) * 65 + k];
            float4 v0 = *(float4*)&Vs[k * 68 + kg * 8];
            float4 v1 = *(float4*)&Vs[k * 68 + kg * 8 + 4];
            float vv[8] = {v0.x, v0.y, v0.z, v0.w, v1.x, v1.y, v1.z, v1.w};
            #pragma unroll
            for (int j = 0; j < 8; j++) {
                acc[0][j] = fmaf(a0, vv[j], acc[0][j]);
                acc[1][j] = fmaf(a1, vv[j], acc[1][j]);
                acc[2][j] = fmaf(a2, vv[j], acc[2][j]);
                acc[3][j] = fmaf(a3, vv[j], acc[3][j]);
            }
        }
        __syncthreads();  // protect Ks/Vs/Sc for next edge
    }

    // write context (exclusive per (src, head) -> plain stores)
    #pragma unroll
    for (int i = 0; i < 4; i++) {
        int q = qg * 4 + i;
        float* o = g_ctx + ((size_t)src * SS + q) * DD + h * HDIM + kg * 8;
        *(float4*)o       = make_float4(acc[i][0], acc[i][1], acc[i][2], acc[i][3]);
        *(float4*)(o + 4) = make_float4(acc[i][4], acc[i][5], acc[i][6], acc[i][7]);
    }
}

// ---------------- launcher ----------------
extern "C" void kernel_launch(void* const* d_in, const int* in_sizes, int n_in,
                              void* d_out, int out_size) {
    const float* nf = (const float*)d_in[0];
    const float* nm = (const float*)d_in[1];
    const float* lw = (const float*)d_in[2];
    const float* lb = (const float*)d_in[3];
    const float* wq = (const float*)d_in[4];
    const float* bq = (const float*)d_in[5];
    const float* wk = (const float*)d_in[6];
    const float* bk = (const float*)d_in[7];
    const float* wv = (const float*)d_in[8];
    const float* bv = (const float*)d_in[9];
    const float* wo = (const float*)d_in[10];
    const float* bo = (const float*)d_in[11];
    const int* ei32 = (const int*)d_in[13];   // edge_index; dtype detected on device
    float* out = (float*)d_out;

    float* p_xn;  cudaGetSymbolAddress((void**)&p_xn,  g_xn);
    float* p_q;   cudaGetSymbolAddress((void**)&p_q,   g_q);
    float* p_k;   cudaGetSymbolAddress((void**)&p_k,   g_k);
    float* p_v;   cudaGetSymbolAddress((void**)&p_v,   g_v);
    float* p_ctx; cudaGetSymbolAddress((void**)&p_ctx, g_ctx);

    // 0. edge dtype detection (int32 vs int64)
    detect_kernel<<<1, 256>>>(ei32);

    // 1. LayerNorm
    ln_kernel<<<MROWS / 8, 256>>>(nf, lw, lb);

    // 2. CSR build (deterministic)
    csr_zero<<<1, 1024>>>();
    csr_hist<<<EE / 256, 256>>>(ei32);
    csr_scan<<<1, 1024>>>();
    csr_scatter<<<EE / 256, 256>>>(ei32);

    // 3. Q/K/V projections
    dim3 gg(4, 512);
    gemm_kernel<<<gg, 256>>>(p_xn, wq, bq, p_q, nullptr, nullptr);
    gemm_kernel<<<gg, 256>>>(p_xn, wk, bk, p_k, nullptr, nullptr);
    gemm_kernel<<<gg, 256>>>(p_xn, wv, bv, p_v, nullptr, nullptr);

    // 4. per-edge attention, accumulated per (src, head)
    static const int ATTN_SMEM = 17280 * 4;  // 69120 B
    cudaFuncSetAttribute(attn_kernel, cudaFuncAttributeMaxDynamicSharedMemorySize, ATTN_SMEM);
    attn_kernel<<<NN * HH, 128, ATTN_SMEM>>>(nm);

    // 5. output projection + residual + mask (fused)
    gemm_kernel<<<gg, 256>>>(p_ctx, wo, bo, out, nf, nm);
}

// round 3
// speedup vs baseline: 1.4193x; 1.4193x over previous
#include <cuda_runtime.h>
#include <cstdint>

// Problem constants (fixed by the reference)
#define NN 1024
#define SS 64
#define DD 256
#define HH 4
#define HDIM 64
#define EE 4096
#define MROWS (NN * SS)   // 65536

// ---------------- scratch (device globals; no allocs allowed) ----------------
__device__ float g_xn[MROWS * DD];    // layernormed features
__device__ float g_q[MROWS * DD];
__device__ float g_k[MROWS * DD];
__device__ float g_v[MROWS * DD];
__device__ float g_ctx[MROWS * DD];   // per-src summed context (pre out-proj)
__device__ uint32_t g_wt[4 * DD * DD];  // pre-transposed+tf32 weights [n][k]
__device__ int g_deg[NN];
__device__ int g_off[NN + 1];
__device__ int g_adj[EE];             // dst ids grouped by src, deterministic order
__device__ int g_step;                // 1 if edge_index is int32, 2 if int64

// ---------------- tf32 / mma helpers ----------------
__device__ __forceinline__ uint32_t f2tf32(float x) {
    uint32_t r;
    asm("cvt.rna.tf32.f32 %0, %1;" : "=r"(r) : "f"(x));
    return r;
}

__device__ __forceinline__ void ldsm4(uint32_t* r, uint32_t addr) {
    asm volatile("ldmatrix.sync.aligned.m8n8.x4.shared.b16 {%0,%1,%2,%3}, [%4];\n"
                 : "=r"(r[0]), "=r"(r[1]), "=r"(r[2]), "=r"(r[3]) : "r"(addr));
}

__device__ __forceinline__ void mma_tf32(float* d, const uint32_t* a, const uint32_t* b) {
    asm volatile(
        "mma.sync.aligned.m16n8k8.row.col.f32.tf32.tf32.f32 "
        "{%0,%1,%2,%3}, {%4,%5,%6,%7}, {%8,%9}, {%0,%1,%2,%3};\n"
        : "+f"(d[0]), "+f"(d[1]), "+f"(d[2]), "+f"(d[3])
        : "r"(a[0]), "r"(a[1]), "r"(a[2]), "r"(a[3]), "r"(b[0]), "r"(b[1]));
}

// ---------------- edge dtype detection ----------------
__global__ void detect_kernel(const int* __restrict__ ei32) {
    int nz = 0;
    for (int i = threadIdx.x; i < EE; i += blockDim.x)
        nz |= (ei32[2 * i + 1] != 0);
    nz = __syncthreads_or(nz);
    if (threadIdx.x == 0) g_step = nz ? 1 : 2;
}

__device__ __forceinline__ int edge_val(const int* __restrict__ ei32, int row, int e) {
    return ei32[g_step * (row * EE + e)];
}

// ---------------- weight transpose + tf32 convert: wt[n][k] = tf32(w[k][n]) --
__global__ void wt_kernel(const float* __restrict__ w, uint32_t* __restrict__ wt) {
    int n = blockIdx.x;
    for (int k = threadIdx.x; k < DD; k += blockDim.x)
        wt[n * DD + k] = f2tf32(w[k * DD + n]);
}

// ---------------- LayerNorm: one warp per row of 256 ----------------
__global__ __launch_bounds__(256) void ln_kernel(const float* __restrict__ x,
                                                 const float* __restrict__ w,
                                                 const float* __restrict__ b) {
    int warp = (blockIdx.x * blockDim.x + threadIdx.x) >> 5;
    int lane = threadIdx.x & 31;
    if (warp >= MROWS) return;
    const float* xr = x + (size_t)warp * DD + lane * 8;
    float4 a = *(const float4*)xr;
    float4 c = *(const float4*)(xr + 4);
    float s  = a.x + a.y + a.z + a.w + c.x + c.y + c.z + c.w;
    float s2 = a.x*a.x + a.y*a.y + a.z*a.z + a.w*a.w
             + c.x*c.x + c.y*c.y + c.z*c.z + c.w*c.w;
    #pragma unroll
    for (int o = 16; o > 0; o >>= 1) {
        s  += __shfl_xor_sync(0xffffffffu, s,  o);
        s2 += __shfl_xor_sync(0xffffffffu, s2, o);
    }
    float mu  = s * (1.0f / DD);
    float var = s2 * (1.0f / DD) - mu * mu;
    float r = rsqrtf(var + 1e-5f);
    float4 w0 = *(const float4*)(w + lane * 8);
    float4 w1 = *(const float4*)(w + lane * 8 + 4);
    float4 b0 = *(const float4*)(b + lane * 8);
    float4 b1 = *(const float4*)(b + lane * 8 + 4);
    float* o = g_xn + (size_t)warp * DD + lane * 8;
    float4 o0, o1;
    o0.x = (a.x - mu) * r * w0.x + b0.x;  o0.y = (a.y - mu) * r * w0.y + b0.y;
    o0.z = (a.z - mu) * r * w0.z + b0.z;  o0.w = (a.w - mu) * r * w0.w + b0.w;
    o1.x = (c.x - mu) * r * w1.x + b1.x;  o1.y = (c.y - mu) * r * w1.y + b1.y;
    o1.z = (c.z - mu) * r * w1.z + b1.z;  o1.w = (c.w - mu) * r * w1.w + b1.w;
    *(float4*)o = o0;
    *(float4*)(o + 4) = o1;
}

// ---------------- CSR build (deterministic edge order per src) ----------------
__global__ void csr_zero() { if (threadIdx.x < NN) g_deg[threadIdx.x] = 0; }

__global__ void csr_hist(const int* __restrict__ ei32) {
    int e = blockIdx.x * blockDim.x + threadIdx.x;
    if (e < EE) atomicAdd(&g_deg[edge_val(ei32, 0, e)], 1);
}

__global__ void csr_scan() {  // one block, NN threads
    __shared__ int s[NN];
    int t = threadIdx.x;
    s[t] = g_deg[t];
    __syncthreads();
    for (int o = 1; o < NN; o <<= 1) {
        int v = (t >= o) ? s[t - o] : 0;
        __syncthreads();
        s[t] += v;
        __syncthreads();
    }
    g_off[t + 1] = s[t];
    if (t == 0) g_off[0] = 0;
}

__global__ void csr_scatter(const int* __restrict__ ei32) {
    int e = blockIdx.x * blockDim.x + threadIdx.x;
    if (e >= EE) return;
    int src = edge_val(ei32, 0, e);
    int cnt = 0;  // rank among earlier edges with same src -> deterministic
    for (int j = 0; j < e; j++) cnt += (edge_val(ei32, 0, j) == src);
    g_adj[g_off[src] + cnt] = edge_val(ei32, 1, e);
}

// ---------------- tf32 tensor-core GEMM ----------------
// C[M,256] = A[M,256] @ W[256,256] + bias ; optional (C+resid)*mask epilogue.
// W supplied pre-transposed+tf32 as wt[n][k]. CTA tile 128x64, 8 warps 4Mx2N,
// warp tile 32x32 via m16n8k8 fragments. Smem row stride 144B => conflict-free
// ldmatrix (144 mod 128 = 16).
__global__ __launch_bounds__(256) void gemm_tc_kernel(const float* __restrict__ A,
                                                      const uint32_t* __restrict__ wt,
                                                      const float* __restrict__ bias,
                                                      float* __restrict__ C,
                                                      const float* __restrict__ resid,
                                                      const float* __restrict__ mask) {
    __shared__ __align__(16) uint32_t As[128 * 36];  // [m][k], stride 36 u32 = 144B
    __shared__ __align__(16) uint32_t Ws[64 * 36];   // [n][k], stride 36 u32

    int tid = threadIdx.x;
    int wid = tid >> 5, lane = tid & 31;
    int m0 = blockIdx.y * 128, n0 = blockIdx.x * 64;
    int mbase = (wid & 3) * 32;   // warp M offset within CTA
    int nbase = (wid >> 2) * 32;  // warp N offset within CTA

    // ldmatrix lane-address components
    int grp = lane >> 3, lrow = lane & 7;
    int rowA  = ((grp & 1) << 3) + lrow;   // a0:(+0,k0) a1:(+8,k0) a2:(+0,k0+16B) a3:(+8,+16B)
    int koffA = (grp >> 1) << 4;           // bytes
    int rowB  = ((grp >> 1) << 3) + lrow;  // b-tiles: (n+0,k0),(n+0,+16B),(n+8,k0),(n+8,+16B)
    int koffB = (grp & 1) << 4;

    uint32_t as_base = (uint32_t)__cvta_generic_to_shared(As);
    uint32_t ws_base = (uint32_t)__cvta_generic_to_shared(Ws);
    uint32_t aAddr = as_base + (mbase + rowA) * 144 + koffA;
    uint32_t bAddr = ws_base + (nbase + rowB) * 144 + koffB;

    float acc[2][4][4];
    #pragma unroll
    for (int mt = 0; mt < 2; mt++)
        #pragma unroll
        for (int nt = 0; nt < 4; nt++)
            #pragma unroll
            for (int v = 0; v < 4; v++) acc[mt][nt][v] = 0.0f;

    for (int gk0 = 0; gk0 < DD; gk0 += 32) {
        // stage A (convert fp32 -> tf32)
        #pragma unroll
        for (int i = 0; i < 4; i++) {
            int id = tid + i * 256;          // 0..1023 => 128 rows x 8 float4
            int r = id >> 3, c4 = id & 7;
            float4 v = *(const float4*)(A + (size_t)(m0 + r) * DD + gk0 + c4 * 4);
            uint4 u = make_uint4(f2tf32(v.x), f2tf32(v.y), f2tf32(v.z), f2tf32(v.w));
            *(uint4*)((char*)As + r * 144 + c4 * 16) = u;
        }
        // stage W (already tf32, already [n][k])
        #pragma unroll
        for (int i = 0; i < 2; i++) {
            int id = tid + i * 256;          // 0..511 => 64 rows x 8 uint4
            int n = id >> 3, c4 = id & 7;
            uint4 u = *(const uint4*)(wt + (size_t)(n0 + n) * DD + gk0 + c4 * 4);
            *(uint4*)((char*)Ws + n * 144 + c4 * 16) = u;
        }
        __syncthreads();

        #pragma unroll
        for (int kb = 0; kb < 4; kb++) {     // 4 k-steps of 8
            uint32_t af[2][4], bf[2][4];
            ldsm4(af[0], aAddr + kb * 32);
            ldsm4(af[1], aAddr + 16 * 144 + kb * 32);
            ldsm4(bf[0], bAddr + kb * 32);
            ldsm4(bf[1], bAddr + 16 * 144 + kb * 32);
            #pragma unroll
            for (int mt = 0; mt < 2; mt++) {
                mma_tf32(acc[mt][0], af[mt], &bf[0][0]);
                mma_tf32(acc[mt][1], af[mt], &bf[0][2]);
                mma_tf32(acc[mt][2], af[mt], &bf[1][0]);
                mma_tf32(acc[mt][3], af[mt], &bf[1][2]);
            }
        }
        __syncthreads();
    }

    // epilogue: c0=(g,2t) c1=(g,2t+1) c2=(g+8,2t) c3=(g+8,2t+1)
    int g = lane >> 2, t2 = (lane & 3) * 2;
    #pragma unroll
    for (int mt = 0; mt < 2; mt++) {
        #pragma unroll
        for (int half = 0; half < 2; half++) {
            int m = m0 + mbase + mt * 16 + g + half * 8;
            float mk = resid ? mask[m] : 0.0f;
            #pragma unroll
            for (int nt = 0; nt < 4; nt++) {
                int n = n0 + nbase + nt * 8 + t2;
                float2 bb = *(const float2*)(bias + n);
                float cx = acc[mt][nt][half * 2 + 0] + bb.x;
                float cy = acc[mt][nt][half * 2 + 1] + bb.y;
                if (resid) {
                    float2 rv = *(const float2*)(resid + (size_t)m * DD + n);
                    cx = (cx + rv.x) * mk;
                    cy = (cy + rv.y) * mk;
                }
                *(float2*)(C + (size_t)m * DD + n) = make_float2(cx, cy);
            }
        }
    }
}

// ---------------- per-(src,head) edge attention (unchanged fp32) ------------
__global__ __launch_bounds__(128) void attn_kernel(const float* __restrict__ masks) {
    extern __shared__ __align__(16) float sm[];
    float* Qs  = sm;            // 64 x (stride 68)
    float* Ks  = sm + 4352;
    float* Vs  = sm + 8704;
    float* Sc  = sm + 13056;    // 64 x (stride 65) attention probs
    float* kmS = sm + 17216;    // 64 key masks

    int src = blockIdx.x >> 2;
    int h   = blockIdx.x & 3;
    int tid = threadIdx.x;
    int qg = tid >> 3;          // 16 groups of 4 q-rows
    int kg = tid & 7;           // 8 groups

    {   // load Q tile [64 x 64] for this head
        int r = tid >> 1, cb = (tid & 1) * 32;
        const float* gq = g_q + ((size_t)src * SS + r) * DD + h * HDIM;
        #pragma unroll
        for (int c = 0; c < 8; c++)
            *(float4*)&Qs[r * 68 + cb + c * 4] = *(const float4*)(gq + cb + c * 4);
    }
    float acc[4][8];
    #pragma unroll
    for (int i = 0; i < 4; i++)
        #pragma unroll
        for (int j = 0; j < 8; j++) acc[i][j] = 0.0f;

    int e0 = g_off[src], e1 = g_off[src + 1];
    __syncthreads();

    for (int e = e0; e < e1; e++) {
        int dst = g_adj[e];
        {   // load K, V tiles + key mask
            int r = tid >> 1, cb = (tid & 1) * 32;
            const float* gk = g_k + ((size_t)dst * SS + r) * DD + h * HDIM;
            const float* gv = g_v + ((size_t)dst * SS + r) * DD + h * HDIM;
            #pragma unroll
            for (int c = 0; c < 8; c++) {
                *(float4*)&Ks[r * 68 + cb + c * 4] = *(const float4*)(gk + cb + c * 4);
                *(float4*)&Vs[r * 68 + cb + c * 4] = *(const float4*)(gv + cb + c * 4);
            }
            if (tid < SS) kmS[tid] = masks[dst * SS + tid];
        }
        __syncthreads();

        float sc[4][8];
        #pragma unroll
        for (int i = 0; i < 4; i++)
            #pragma unroll
            for (int j = 0; j < 8; j++) sc[i][j] = 0.0f;
        #pragma unroll
        for (int d = 0; d < 64; d += 4) {
            float4 qv[4], kv[8];
            #pragma unroll
            for (int i = 0; i < 4; i++) qv[i] = *(float4*)&Qs[(qg * 4 + i) * 68 + d];
            #pragma unroll
            for (int j = 0; j < 8; j++) kv[j] = *(float4*)&Ks[(j * 8 + kg) * 68 + d];
            #pragma unroll
            for (int i = 0; i < 4; i++)
                #pragma unroll
                for (int j = 0; j < 8; j++) {
                    sc[i][j] = fmaf(qv[i].x, kv[j].x, sc[i][j]);
                    sc[i][j] = fmaf(qv[i].y, kv[j].y, sc[i][j]);
                    sc[i][j] = fmaf(qv[i].z, kv[j].z, sc[i][j]);
                    sc[i][j] = fmaf(qv[i].w, kv[j].w, sc[i][j]);
                }
        }
        float mx[4] = {-1e30f, -1e30f, -1e30f, -1e30f};
        #pragma unroll
        for (int i = 0; i < 4; i++)
            #pragma unroll
            for (int j = 0; j < 8; j++) {
                float km = kmS[j * 8 + kg];
                float s = (km > 0.0f) ? sc[i][j] * 0.125f : -1e30f;
                sc[i][j] = s;
                mx[i] = fmaxf(mx[i], s);
            }
        #pragma unroll
        for (int i = 0; i < 4; i++) {
            mx[i] = fmaxf(mx[i], __shfl_xor_sync(0xffffffffu, mx[i], 1));
            mx[i] = fmaxf(mx[i], __shfl_xor_sync(0xffffffffu, mx[i], 2));
            mx[i] = fmaxf(mx[i], __shfl_xor_sync(0xffffffffu, mx[i], 4));
        }
        float sum[4] = {0.0f, 0.0f, 0.0f, 0.0f};
        #pragma unroll
        for (int i = 0; i < 4; i++)
            #pragma unroll
            for (int j = 0; j < 8; j++) {
                float p = __expf(sc[i][j] - mx[i]) * kmS[j * 8 + kg];
                sc[i][j] = p;
                sum[i] += p;
            }
        #pragma unroll
        for (int i = 0; i < 4; i++) {
            sum[i] += __shfl_xor_sync(0xffffffffu, sum[i], 1);
            sum[i] += __shfl_xor_sync(0xffffffffu, sum[i], 2);
            sum[i] += __shfl_xor_sync(0xffffffffu, sum[i], 4);
            float inv = (sum[i] > 0.0f) ? (1.0f / sum[i]) : 0.0f;
            #pragma unroll
            for (int j = 0; j < 8; j++)
                Sc[(qg * 4 + i) * 65 + j * 8 + kg] = sc[i][j] * inv;
        }
        __syncthreads();

        #pragma unroll 8
        for (int k = 0; k < 64; k++) {
            float a0 = Sc[(qg * 4 + 0) * 65 + k];
            float a1 = Sc[(qg * 4 + 1) * 65 + k];
            float a2 = Sc[(qg * 4 + 2) * 65 + k];
            float a3 = Sc[(qg * 4 + 3) * 65 + k];
            float4 v0 = *(float4*)&Vs[k * 68 + kg * 8];
            float4 v1 = *(float4*)&Vs[k * 68 + kg * 8 + 4];
            float vv[8] = {v0.x, v0.y, v0.z, v0.w, v1.x, v1.y, v1.z, v1.w};
            #pragma unroll
            for (int j = 0; j < 8; j++) {
                acc[0][j] = fmaf(a0, vv[j], acc[0][j]);
                acc[1][j] = fmaf(a1, vv[j], acc[1][j]);
                acc[2][j] = fmaf(a2, vv[j], acc[2][j]);
                acc[3][j] = fmaf(a3, vv[j], acc[3][j]);
            }
        }
        __syncthreads();
    }

    #pragma unroll
    for (int i = 0; i < 4; i++) {
        int q = qg * 4 + i;
        float* o = g_ctx + ((size_t)src * SS + q) * DD + h * HDIM + kg * 8;
        *(float4*)o       = make_float4(acc[i][0], acc[i][1], acc[i][2], acc[i][3]);
        *(float4*)(o + 4) = make_float4(acc[i][4], acc[i][5], acc[i][6], acc[i][7]);
    }
}

// ---------------- launcher ----------------
extern "C" void kernel_launch(void* const* d_in, const int* in_sizes, int n_in,
                              void* d_out, int out_size) {
    const float* nf = (const float*)d_in[0];
    const float* nm = (const float*)d_in[1];
    const float* lw = (const float*)d_in[2];
    const float* lb = (const float*)d_in[3];
    const float* wq = (const float*)d_in[4];
    const float* bq = (const float*)d_in[5];
    const float* wk = (const float*)d_in[6];
    const float* bk = (const float*)d_in[7];
    const float* wv = (const float*)d_in[8];
    const float* bv = (const float*)d_in[9];
    const float* wo = (const float*)d_in[10];
    const float* bo = (const float*)d_in[11];
    const int* ei32 = (const int*)d_in[13];   // edge_index; dtype detected on device
    float* out = (float*)d_out;

    float* p_xn;  cudaGetSymbolAddress((void**)&p_xn,  g_xn);
    float* p_q;   cudaGetSymbolAddress((void**)&p_q,   g_q);
    float* p_k;   cudaGetSymbolAddress((void**)&p_k,   g_k);
    float* p_v;   cudaGetSymbolAddress((void**)&p_v,   g_v);
    float* p_ctx; cudaGetSymbolAddress((void**)&p_ctx, g_ctx);
    uint32_t* p_wt; cudaGetSymbolAddress((void**)&p_wt, g_wt);

    // 0. edge dtype detection (int32 vs int64)
    detect_kernel<<<1, 256>>>(ei32);

    // 0b. weight transposes + tf32 convert (tiny)
    wt_kernel<<<DD, 256>>>(wq, p_wt + 0 * DD * DD);
    wt_kernel<<<DD, 256>>>(wk, p_wt + 1 * DD * DD);
    wt_kernel<<<DD, 256>>>(wv, p_wt + 2 * DD * DD);
    wt_kernel<<<DD, 256>>>(wo, p_wt + 3 * DD * DD);

    // 1. LayerNorm
    ln_kernel<<<MROWS / 8, 256>>>(nf, lw, lb);

    // 2. CSR build (deterministic)
    csr_zero<<<1, 1024>>>();
    csr_hist<<<EE / 256, 256>>>(ei32);
    csr_scan<<<1, 1024>>>();
    csr_scatter<<<EE / 256, 256>>>(ei32);

    // 3. Q/K/V projections (tf32 tensor cores)
    dim3 gg(4, 512);
    gemm_tc_kernel<<<gg, 256>>>(p_xn, p_wt + 0 * DD * DD, bq, p_q, nullptr, nullptr);
    gemm_tc_kernel<<<gg, 256>>>(p_xn, p_wt + 1 * DD * DD, bk, p_k, nullptr, nullptr);
    gemm_tc_kernel<<<gg, 256>>>(p_xn, p_wt + 2 * DD * DD, bv, p_v, nullptr, nullptr);

    // 4. per-edge attention, accumulated per (src, head)
    static const int ATTN_SMEM = 17280 * 4;  // 69120 B
    cudaFuncSetAttribute(attn_kernel, cudaFuncAttributeMaxDynamicSharedMemorySize, ATTN_SMEM);
    attn_kernel<<<NN * HH, 128, ATTN_SMEM>>>(nm);

    // 5. output projection + residual + mask (fused, tf32 tensor cores)
    gemm_tc_kernel<<<gg, 256>>>(p_ctx, p_wt + 3 * DD * DD, bo, out, nf, nm);
}

// round 4
// speedup vs baseline: 1.7810x; 1.2549x over previous
#include <cuda_runtime.h>
#include <cstdint>

// Problem constants (fixed by the reference)
#define NN 1024
#define SS 64
#define DD 256
#define HH 4
#define HDIM 64
#define EE 4096
#define MROWS (NN * SS)   // 65536

// ---------------- scratch (device globals; no allocs allowed) ----------------
__device__ float g_xn[MROWS * DD];    // layernormed features
__device__ float g_q[MROWS * DD];
__device__ float g_k[MROWS * DD];
__device__ float g_v[MROWS * DD];
__device__ float g_ctx[MROWS * DD];   // per-src summed context (pre out-proj)
__device__ uint32_t g_wt[4 * DD * DD];  // pre-transposed+tf32 weights [n][k]
__device__ int g_deg[NN];
__device__ int g_off[NN + 1];
__device__ int g_adj[EE];             // dst ids grouped by src, deterministic order
__device__ int g_len[NN];             // valid-token count per node (prefix mask)
__device__ int g_step;                // 1 if edge_index is int32, 2 if int64

// ---------------- tf32 / mma helpers ----------------
__device__ __forceinline__ uint32_t f2tf32(float x) {
    uint32_t r;
    asm("cvt.rna.tf32.f32 %0, %1;" : "=r"(r) : "f"(x));
    return r;
}

__device__ __forceinline__ void ldsm4(uint32_t* r, uint32_t addr) {
    asm volatile("ldmatrix.sync.aligned.m8n8.x4.shared.b16 {%0,%1,%2,%3}, [%4];\n"
                 : "=r"(r[0]), "=r"(r[1]), "=r"(r[2]), "=r"(r[3]) : "r"(addr));
}

__device__ __forceinline__ void mma_tf32(float* d, const uint32_t* a, const uint32_t* b) {
    asm volatile(
        "mma.sync.aligned.m16n8k8.row.col.f32.tf32.tf32.f32 "
        "{%0,%1,%2,%3}, {%4,%5,%6,%7}, {%8,%9}, {%0,%1,%2,%3};\n"
        : "+f"(d[0]), "+f"(d[1]), "+f"(d[2]), "+f"(d[3])
        : "r"(a[0]), "r"(a[1]), "r"(a[2]), "r"(a[3]), "r"(b[0]), "r"(b[1]));
}

// ---------------- edge dtype detection ----------------
__global__ void detect_kernel(const int* __restrict__ ei32) {
    int nz = 0;
    for (int i = threadIdx.x; i < EE; i += blockDim.x)
        nz |= (ei32[2 * i + 1] != 0);
    nz = __syncthreads_or(nz);
    if (threadIdx.x == 0) g_step = nz ? 1 : 2;
}

__device__ __forceinline__ int edge_val(const int* __restrict__ ei32, int row, int e) {
    return ei32[g_step * (row * EE + e)];
}

// ---------------- weight transpose + tf32 convert: wt[n][k] = tf32(w[k][n]) --
__global__ void wt_kernel(const float* __restrict__ w, uint32_t* __restrict__ wt) {
    int n = blockIdx.x;
    for (int k = threadIdx.x; k < DD; k += blockDim.x)
        wt[n * DD + k] = f2tf32(w[k * DD + n]);
}

// ---------------- lengths: count of valid (prefix) tokens per node ----------
__global__ void len_kernel(const float* __restrict__ masks) {
    int n = blockIdx.x * blockDim.x + threadIdx.x;
    if (n < NN) {
        int c = 0;
        #pragma unroll 8
        for (int s = 0; s < SS; s++) c += (masks[n * SS + s] > 0.0f);
        g_len[n] = c;
    }
}

// ---------------- LayerNorm: one warp per row of 256 ----------------
__global__ __launch_bounds__(256) void ln_kernel(const float* __restrict__ x,
                                                 const float* __restrict__ w,
                                                 const float* __restrict__ b) {
    int warp = (blockIdx.x * blockDim.x + threadIdx.x) >> 5;
    int lane = threadIdx.x & 31;
    if (warp >= MROWS) return;
    const float* xr = x + (size_t)warp * DD + lane * 8;
    float4 a = *(const float4*)xr;
    float4 c = *(const float4*)(xr + 4);
    float s  = a.x + a.y + a.z + a.w + c.x + c.y + c.z + c.w;
    float s2 = a.x*a.x + a.y*a.y + a.z*a.z + a.w*a.w
             + c.x*c.x + c.y*c.y + c.z*c.z + c.w*c.w;
    #pragma unroll
    for (int o = 16; o > 0; o >>= 1) {
        s  += __shfl_xor_sync(0xffffffffu, s,  o);
        s2 += __shfl_xor_sync(0xffffffffu, s2, o);
    }
    float mu  = s * (1.0f / DD);
    float var = s2 * (1.0f / DD) - mu * mu;
    float r = rsqrtf(var + 1e-5f);
    float4 w0 = *(const float4*)(w + lane * 8);
    float4 w1 = *(const float4*)(w + lane * 8 + 4);
    float4 b0 = *(const float4*)(b + lane * 8);
    float4 b1 = *(const float4*)(b + lane * 8 + 4);
    float* o = g_xn + (size_t)warp * DD + lane * 8;
    float4 o0, o1;
    o0.x = (a.x - mu) * r * w0.x + b0.x;  o0.y = (a.y - mu) * r * w0.y + b0.y;
    o0.z = (a.z - mu) * r * w0.z + b0.z;  o0.w = (a.w - mu) * r * w0.w + b0.w;
    o1.x = (c.x - mu) * r * w1.x + b1.x;  o1.y = (c.y - mu) * r * w1.y + b1.y;
    o1.z = (c.z - mu) * r * w1.z + b1.z;  o1.w = (c.w - mu) * r * w1.w + b1.w;
    *(float4*)o = o0;
    *(float4*)(o + 4) = o1;
}

// ---------------- CSR build (deterministic edge order per src) ----------------
__global__ void csr_zero() { if (threadIdx.x < NN) g_deg[threadIdx.x] = 0; }

__global__ void csr_hist(const int* __restrict__ ei32) {
    int e = blockIdx.x * blockDim.x + threadIdx.x;
    if (e < EE) atomicAdd(&g_deg[edge_val(ei32, 0, e)], 1);
}

__global__ void csr_scan() {  // one block, NN threads
    __shared__ int s[NN];
    int t = threadIdx.x;
    s[t] = g_deg[t];
    __syncthreads();
    for (int o = 1; o < NN; o <<= 1) {
        int v = (t >= o) ? s[t - o] : 0;
        __syncthreads();
        s[t] += v;
        __syncthreads();
    }
    g_off[t + 1] = s[t];
    if (t == 0) g_off[0] = 0;
}

__global__ void csr_scatter(const int* __restrict__ ei32) {
    int e = blockIdx.x * blockDim.x + threadIdx.x;
    if (e >= EE) return;
    int src = edge_val(ei32, 0, e);
    int cnt = 0;  // rank among earlier edges with same src -> deterministic
    for (int j = 0; j < e; j++) cnt += (edge_val(ei32, 0, j) == src);
    g_adj[g_off[src] + cnt] = edge_val(ei32, 1, e);
}

// ---------------- tf32 tensor-core GEMM (unchanged from R3) ----------------
__global__ __launch_bounds__(256) void gemm_tc_kernel(const float* __restrict__ A,
                                                      const uint32_t* __restrict__ wt,
                                                      const float* __restrict__ bias,
                                                      float* __restrict__ C,
                                                      const float* __restrict__ resid,
                                                      const float* __restrict__ mask) {
    __shared__ __align__(16) uint32_t As[128 * 36];  // [m][k], stride 36 u32 = 144B
    __shared__ __align__(16) uint32_t Ws[64 * 36];   // [n][k]

    int tid = threadIdx.x;
    int wid = tid >> 5, lane = tid & 31;
    int m0 = blockIdx.y * 128, n0 = blockIdx.x * 64;
    int mbase = (wid & 3) * 32;
    int nbase = (wid >> 2) * 32;

    int grp = lane >> 3, lrow = lane & 7;
    int rowA  = ((grp & 1) << 3) + lrow;
    int koffA = (grp >> 1) << 4;
    int rowB  = ((grp >> 1) << 3) + lrow;
    int koffB = (grp & 1) << 4;

    uint32_t as_base = (uint32_t)__cvta_generic_to_shared(As);
    uint32_t ws_base = (uint32_t)__cvta_generic_to_shared(Ws);
    uint32_t aAddr = as_base + (mbase + rowA) * 144 + koffA;
    uint32_t bAddr = ws_base + (nbase + rowB) * 144 + koffB;

    float acc[2][4][4];
    #pragma unroll
    for (int mt = 0; mt < 2; mt++)
        #pragma unroll
        for (int nt = 0; nt < 4; nt++)
            #pragma unroll
            for (int v = 0; v < 4; v++) acc[mt][nt][v] = 0.0f;

    for (int gk0 = 0; gk0 < DD; gk0 += 32) {
        #pragma unroll
        for (int i = 0; i < 4; i++) {
            int id = tid + i * 256;
            int r = id >> 3, c4 = id & 7;
            float4 v = *(const float4*)(A + (size_t)(m0 + r) * DD + gk0 + c4 * 4);
            uint4 u = make_uint4(f2tf32(v.x), f2tf32(v.y), f2tf32(v.z), f2tf32(v.w));
            *(uint4*)((char*)As + r * 144 + c4 * 16) = u;
        }
        #pragma unroll
        for (int i = 0; i < 2; i++) {
            int id = tid + i * 256;
            int n = id >> 3, c4 = id & 7;
            uint4 u = *(const uint4*)(wt + (size_t)(n0 + n) * DD + gk0 + c4 * 4);
            *(uint4*)((char*)Ws + n * 144 + c4 * 16) = u;
        }
        __syncthreads();

        #pragma unroll
        for (int kb = 0; kb < 4; kb++) {
            uint32_t af[2][4], bf[2][4];
            ldsm4(af[0], aAddr + kb * 32);
            ldsm4(af[1], aAddr + 16 * 144 + kb * 32);
            ldsm4(bf[0], bAddr + kb * 32);
            ldsm4(bf[1], bAddr + 16 * 144 + kb * 32);
            #pragma unroll
            for (int mt = 0; mt < 2; mt++) {
                mma_tf32(acc[mt][0], af[mt], &bf[0][0]);
                mma_tf32(acc[mt][1], af[mt], &bf[0][2]);
                mma_tf32(acc[mt][2], af[mt], &bf[1][0]);
                mma_tf32(acc[mt][3], af[mt], &bf[1][2]);
            }
        }
        __syncthreads();
    }

    int g = lane >> 2, t2 = (lane & 3) * 2;
    #pragma unroll
    for (int mt = 0; mt < 2; mt++) {
        #pragma unroll
        for (int half = 0; half < 2; half++) {
            int m = m0 + mbase + mt * 16 + g + half * 8;
            float mk = resid ? mask[m] : 0.0f;
            #pragma unroll
            for (int nt = 0; nt < 4; nt++) {
                int n = n0 + nbase + nt * 8 + t2;
                float2 bb = *(const float2*)(bias + n);
                float cx = acc[mt][nt][half * 2 + 0] + bb.x;
                float cy = acc[mt][nt][half * 2 + 1] + bb.y;
                if (resid) {
                    float2 rv = *(const float2*)(resid + (size_t)m * DD + n);
                    cx = (cx + rv.x) * mk;
                    cy = (cy + rv.y) * mk;
                }
                *(float2*)(C + (size_t)m * DD + n) = make_float2(cx, cy);
            }
        }
    }
}

// ---------------- per-edge score+softmax, templated on #k-tiles ----------------
// NJ in {2,4,6,8}: computes scores for k tiles j < NJ (k = j*8+kg), masks,
// softmax over valid keys, writes probs to Sc. gm = shuffle mask of the
// 8-lane row group.
template <int NJ>
__device__ __forceinline__ void edge_compute(const float* __restrict__ Qs,
                                             const float* __restrict__ Ks,
                                             const float* __restrict__ kmS,
                                             float* __restrict__ Sc,
                                             int qg, int kg, unsigned gm) {
    float sc[4][NJ];
    #pragma unroll
    for (int i = 0; i < 4; i++)
        #pragma unroll
        for (int j = 0; j < NJ; j++) sc[i][j] = 0.0f;

    #pragma unroll
    for (int d = 0; d < 64; d += 4) {
        float4 qv[4], kv[NJ];
        #pragma unroll
        for (int i = 0; i < 4; i++) qv[i] = *(const float4*)&Qs[(qg * 4 + i) * 68 + d];
        #pragma unroll
        for (int j = 0; j < NJ; j++) kv[j] = *(const float4*)&Ks[(j * 8 + kg) * 68 + d];
        #pragma unroll
        for (int i = 0; i < 4; i++)
            #pragma unroll
            for (int j = 0; j < NJ; j++) {
                sc[i][j] = fmaf(qv[i].x, kv[j].x, sc[i][j]);
                sc[i][j] = fmaf(qv[i].y, kv[j].y, sc[i][j]);
                sc[i][j] = fmaf(qv[i].z, kv[j].z, sc[i][j]);
                sc[i][j] = fmaf(qv[i].w, kv[j].w, sc[i][j]);
            }
    }
    float mx[4] = {-1e30f, -1e30f, -1e30f, -1e30f};
    #pragma unroll
    for (int i = 0; i < 4; i++)
        #pragma unroll
        for (int j = 0; j < NJ; j++) {
            float km = kmS[j * 8 + kg];
            float s = (km > 0.0f) ? sc[i][j] * 0.125f : -1e30f;
            sc[i][j] = s;
            mx[i] = fmaxf(mx[i], s);
        }
    #pragma unroll
    for (int i = 0; i < 4; i++) {
        mx[i] = fmaxf(mx[i], __shfl_xor_sync(gm, mx[i], 1));
        mx[i] = fmaxf(mx[i], __shfl_xor_sync(gm, mx[i], 2));
        mx[i] = fmaxf(mx[i], __shfl_xor_sync(gm, mx[i], 4));
    }
    float sum[4] = {0.0f, 0.0f, 0.0f, 0.0f};
    #pragma unroll
    for (int i = 0; i < 4; i++)
        #pragma unroll
        for (int j = 0; j < NJ; j++) {
            float p = __expf(sc[i][j] - mx[i]) * kmS[j * 8 + kg];
            sc[i][j] = p;
            sum[i] += p;
        }
    #pragma unroll
    for (int i = 0; i < 4; i++) {
        sum[i] += __shfl_xor_sync(gm, sum[i], 1);
        sum[i] += __shfl_xor_sync(gm, sum[i], 2);
        sum[i] += __shfl_xor_sync(gm, sum[i], 4);
        float inv = (sum[i] > 0.0f) ? (1.0f / sum[i]) : 0.0f;
        #pragma unroll
        for (int j = 0; j < NJ; j++)
            Sc[(qg * 4 + i) * 65 + j * 8 + kg] = sc[i][j] * inv;
    }
}

// ---------------- per-(src,head) edge attention with length bounds ----------
__global__ __launch_bounds__(128) void attn_kernel(const float* __restrict__ masks) {
    extern __shared__ __align__(16) float sm[];
    float* Qs  = sm;            // 64 x (stride 68)
    float* Ks  = sm + 4352;
    float* Vs  = sm + 8704;
    float* Sc  = sm + 13056;    // 64 x (stride 65) attention probs
    float* kmS = sm + 17216;    // 64 key masks

    int src = blockIdx.x >> 2;
    int h   = blockIdx.x & 3;
    int tid = threadIdx.x;
    int qg = tid >> 3;          // 16 groups of 4 q-rows
    int kg = tid & 7;           // 8 lanes per row group
    unsigned gm = 0xffu << (((tid & 31) >> 3) * 8);  // shuffle mask of 8-lane group

    int q_len = g_len[src];
    bool qact = (qg * 4 < q_len);

    {   // load Q tile [64 x 64] for this head (full; one-time cost)
        int r = tid >> 1, cb = (tid & 1) * 32;
        const float* gq = g_q + ((size_t)src * SS + r) * DD + h * HDIM;
        #pragma unroll
        for (int c = 0; c < 8; c++)
            *(float4*)&Qs[r * 68 + cb + c * 4] = *(const float4*)(gq + cb + c * 4);
    }
    float acc[4][8];
    #pragma unroll
    for (int i = 0; i < 4; i++)
        #pragma unroll
        for (int j = 0; j < 8; j++) acc[i][j] = 0.0f;

    int e0 = g_off[src], e1 = g_off[src + 1];
    __syncthreads();

    for (int e = e0; e < e1; e++) {
        int dst = g_adj[e];
        int k_len = g_len[dst];
        int nt8 = (k_len + 7) >> 3;   // 8-wide k tiles actually needed
        int kup = nt8 << 3;
        int nc  = (kup + 15) >> 4;    // 16-wide chunks: 1..4
        int rup = nc << 4;            // rows to stage (<= 64, valid gmem)

        {   // load K, V rows < rup + full key mask
            int r = tid >> 1, cb = (tid & 1) * 32;
            if (r < rup) {
                const float* gk = g_k + ((size_t)dst * SS + r) * DD + h * HDIM;
                const float* gv = g_v + ((size_t)dst * SS + r) * DD + h * HDIM;
                #pragma unroll
                for (int c = 0; c < 8; c++) {
                    *(float4*)&Ks[r * 68 + cb + c * 4] = *(const float4*)(gk + cb + c * 4);
                    *(float4*)&Vs[r * 68 + cb + c * 4] = *(const float4*)(gv + cb + c * 4);
                }
            }
            if (tid < SS) kmS[tid] = masks[dst * SS + tid];
        }
        __syncthreads();

        if (qact) {
            switch (nc) {
                case 1:  edge_compute<2>(Qs, Ks, kmS, Sc, qg, kg, gm); break;
                case 2:  edge_compute<4>(Qs, Ks, kmS, Sc, qg, kg, gm); break;
                case 3:  edge_compute<6>(Qs, Ks, kmS, Sc, qg, kg, gm); break;
                default: edge_compute<8>(Qs, Ks, kmS, Sc, qg, kg, gm); break;
            }
        }
        __syncthreads();

        if (qact) {
            // ctx += attn @ V, k bounded by kup (probs beyond are 0/unwritten)
            #pragma unroll 8
            for (int k = 0; k < kup; k++) {
                float a0 = Sc[(qg * 4 + 0) * 65 + k];
                float a1 = Sc[(qg * 4 + 1) * 65 + k];
                float a2 = Sc[(qg * 4 + 2) * 65 + k];
                float a3 = Sc[(qg * 4 + 3) * 65 + k];
                float4 v0 = *(float4*)&Vs[k * 68 + kg * 8];
                float4 v1 = *(float4*)&Vs[k * 68 + kg * 8 + 4];
                float vv[8] = {v0.x, v0.y, v0.z, v0.w, v1.x, v1.y, v1.z, v1.w};
                #pragma unroll
                for (int j = 0; j < 8; j++) {
                    acc[0][j] = fmaf(a0, vv[j], acc[0][j]);
                    acc[1][j] = fmaf(a1, vv[j], acc[1][j]);
                    acc[2][j] = fmaf(a2, vv[j], acc[2][j]);
                    acc[3][j] = fmaf(a3, vv[j], acc[3][j]);
                }
            }
        }
        __syncthreads();  // protect Ks/Vs/Sc for next edge
    }

    // write context (exclusive per (src, head); zeros for inactive rows)
    #pragma unroll
    for (int i = 0; i < 4; i++) {
        int q = qg * 4 + i;
        float* o = g_ctx + ((size_t)src * SS + q) * DD + h * HDIM + kg * 8;
        *(float4*)o       = make_float4(acc[i][0], acc[i][1], acc[i][2], acc[i][3]);
        *(float4*)(o + 4) = make_float4(acc[i][4], acc[i][5], acc[i][6], acc[i][7]);
    }
}

// ---------------- launcher ----------------
extern "C" void kernel_launch(void* const* d_in, const int* in_sizes, int n_in,
                              void* d_out, int out_size) {
    const float* nf = (const float*)d_in[0];
    const float* nm = (const float*)d_in[1];
    const float* lw = (const float*)d_in[2];
    const float* lb = (const float*)d_in[3];
    const float* wq = (const float*)d_in[4];
    const float* bq = (const float*)d_in[5];
    const float* wk = (const float*)d_in[6];
    const float* bk = (const float*)d_in[7];
    const float* wv = (const float*)d_in[8];
    const float* bv = (const float*)d_in[9];
    const float* wo = (const float*)d_in[10];
    const float* bo = (const float*)d_in[11];
    const int* ei32 = (const int*)d_in[13];   // edge_index; dtype detected on device
    float* out = (float*)d_out;

    float* p_xn;  cudaGetSymbolAddress((void**)&p_xn,  g_xn);
    float* p_q;   cudaGetSymbolAddress((void**)&p_q,   g_q);
    float* p_k;   cudaGetSymbolAddress((void**)&p_k,   g_k);
    float* p_v;   cudaGetSymbolAddress((void**)&p_v,   g_v);
    float* p_ctx; cudaGetSymbolAddress((void**)&p_ctx, g_ctx);
    uint32_t* p_wt; cudaGetSymbolAddress((void**)&p_wt, g_wt);

    // 0. edge dtype detection + lengths + weight prep
    detect_kernel<<<1, 256>>>(ei32);
    len_kernel<<<4, 256>>>(nm);
    wt_kernel<<<DD, 256>>>(wq, p_wt + 0 * DD * DD);
    wt_kernel<<<DD, 256>>>(wk, p_wt + 1 * DD * DD);
    wt_kernel<<<DD, 256>>>(wv, p_wt + 2 * DD * DD);
    wt_kernel<<<DD, 256>>>(wo, p_wt + 3 * DD * DD);

    // 1. LayerNorm
    ln_kernel<<<MROWS / 8, 256>>>(nf, lw, lb);

    // 2. CSR build (deterministic)
    csr_zero<<<1, 1024>>>();
    csr_hist<<<EE / 256, 256>>>(ei32);
    csr_scan<<<1, 1024>>>();
    csr_scatter<<<EE / 256, 256>>>(ei32);

    // 3. Q/K/V projections (tf32 tensor cores)
    dim3 gg(4, 512);
    gemm_tc_kernel<<<gg, 256>>>(p_xn, p_wt + 0 * DD * DD, bq, p_q, nullptr, nullptr);
    gemm_tc_kernel<<<gg, 256>>>(p_xn, p_wt + 1 * DD * DD, bk, p_k, nullptr, nullptr);
    gemm_tc_kernel<<<gg, 256>>>(p_xn, p_wt + 2 * DD * DD, bv, p_v, nullptr, nullptr);

    // 4. per-edge attention with length bounds
    static const int ATTN_SMEM = 17280 * 4;  // 69120 B
    cudaFuncSetAttribute(attn_kernel, cudaFuncAttributeMaxDynamicSharedMemorySize, ATTN_SMEM);
    attn_kernel<<<NN * HH, 128, ATTN_SMEM>>>(nm);

    // 5. output projection + residual + mask (fused, tf32 tensor cores)
    gemm_tc_kernel<<<gg, 256>>>(p_ctx, p_wt + 3 * DD * DD, bo, out, nf, nm);
}

// round 5
// speedup vs baseline: 2.3210x; 1.3032x over previous
#include <cuda_runtime.h>
#include <cuda_bf16.h>
#include <cstdint>

// Problem constants (fixed by the reference)
#define NN 1024
#define SS 64
#define DD 256
#define HH 4
#define HDIM 64
#define EE 4096
#define MROWS (NN * SS)   // 65536
#define RS 40             // smem row stride in bf16 (80 B) -> conflict-free ldmatrix

// ---------------- scratch (device globals; no allocs allowed) ----------------
__device__ __nv_bfloat16 g_xnb[MROWS * DD];   // layernormed features (bf16)
__device__ float g_q[MROWS * DD];
__device__ float g_k[MROWS * DD];
__device__ float g_v[MROWS * DD];
__device__ __nv_bfloat16 g_ctxb[MROWS * DD];  // per-src summed context (bf16)
__device__ __nv_bfloat16 g_wtb[4 * DD * DD];  // stacked weights [n][k]: wq,wk,wv,wo
__device__ int g_deg[NN];
__device__ int g_off[NN + 1];
__device__ int g_adj[EE];
__device__ int g_len[NN];
__device__ int g_step;

// ---------------- mma helpers ----------------
__device__ __forceinline__ void ldsm4(uint32_t* r, uint32_t addr) {
    asm volatile("ldmatrix.sync.aligned.m8n8.x4.shared.b16 {%0,%1,%2,%3}, [%4];\n"
                 : "=r"(r[0]), "=r"(r[1]), "=r"(r[2]), "=r"(r[3]) : "r"(addr));
}

__device__ __forceinline__ void mma_bf16(float* d, const uint32_t* a, const uint32_t* b) {
    asm volatile(
        "mma.sync.aligned.m16n8k16.row.col.f32.bf16.bf16.f32 "
        "{%0,%1,%2,%3}, {%4,%5,%6,%7}, {%8,%9}, {%0,%1,%2,%3};\n"
        : "+f"(d[0]), "+f"(d[1]), "+f"(d[2]), "+f"(d[3])
        : "r"(a[0]), "r"(a[1]), "r"(a[2]), "r"(a[3]), "r"(b[0]), "r"(b[1]));
}

#define CP16(dst, src) \
    asm volatile("cp.async.cg.shared.global [%0], [%1], 16;\n" :: "r"(dst), "l"(src))
#define CP_COMMIT() asm volatile("cp.async.commit_group;\n" ::: "memory")
#define CP_WAIT0()  asm volatile("cp.async.wait_group 0;\n" ::: "memory")

// ---------------- edge dtype detection ----------------
__global__ void detect_kernel(const int* __restrict__ ei32) {
    int nz = 0;
    for (int i = threadIdx.x; i < EE; i += blockDim.x)
        nz |= (ei32[2 * i + 1] != 0);
    nz = __syncthreads_or(nz);
    if (threadIdx.x == 0) g_step = nz ? 1 : 2;
}

__device__ __forceinline__ int edge_val(const int* __restrict__ ei32, int row, int e) {
    return ei32[g_step * (row * EE + e)];
}

// ---------------- weights: stacked transpose + bf16: wtb[n][k] ----------------
__global__ void wtb_kernel(const float* __restrict__ wq, const float* __restrict__ wk,
                           const float* __restrict__ wv, const float* __restrict__ wo) {
    int bx = blockIdx.x;  // 0..1023
    const float* w = (bx < 256) ? wq : (bx < 512) ? wk : (bx < 768) ? wv : wo;
    int n = bx & 255;
    for (int k = threadIdx.x; k < DD; k += blockDim.x)
        g_wtb[bx * DD + k] = __float2bfloat16(w[k * DD + n]);
}

// ---------------- lengths ----------------
__global__ void len_kernel(const float* __restrict__ masks) {
    int n = blockIdx.x * blockDim.x + threadIdx.x;
    if (n < NN) {
        int c = 0;
        #pragma unroll 8
        for (int s = 0; s < SS; s++) c += (masks[n * SS + s] > 0.0f);
        g_len[n] = c;
    }
}

// ---------------- LayerNorm -> bf16 output ----------------
__global__ __launch_bounds__(256) void ln_kernel(const float* __restrict__ x,
                                                 const float* __restrict__ w,
                                                 const float* __restrict__ b) {
    int warp = (blockIdx.x * blockDim.x + threadIdx.x) >> 5;
    int lane = threadIdx.x & 31;
    if (warp >= MROWS) return;
    const float* xr = x + (size_t)warp * DD + lane * 8;
    float4 a = *(const float4*)xr;
    float4 c = *(const float4*)(xr + 4);
    float s  = a.x + a.y + a.z + a.w + c.x + c.y + c.z + c.w;
    float s2 = a.x*a.x + a.y*a.y + a.z*a.z + a.w*a.w
             + c.x*c.x + c.y*c.y + c.z*c.z + c.w*c.w;
    #pragma unroll
    for (int o = 16; o > 0; o >>= 1) {
        s  += __shfl_xor_sync(0xffffffffu, s,  o);
        s2 += __shfl_xor_sync(0xffffffffu, s2, o);
    }
    float mu  = s * (1.0f / DD);
    float var = s2 * (1.0f / DD) - mu * mu;
    float r = rsqrtf(var + 1e-5f);
    float4 w0 = *(const float4*)(w + lane * 8);
    float4 w1 = *(const float4*)(w + lane * 8 + 4);
    float4 b0 = *(const float4*)(b + lane * 8);
    float4 b1 = *(const float4*)(b + lane * 8 + 4);
    float o0x = (a.x - mu) * r * w0.x + b0.x, o0y = (a.y - mu) * r * w0.y + b0.y;
    float o0z = (a.z - mu) * r * w0.z + b0.z, o0w = (a.w - mu) * r * w0.w + b0.w;
    float o1x = (c.x - mu) * r * w1.x + b1.x, o1y = (c.y - mu) * r * w1.y + b1.y;
    float o1z = (c.z - mu) * r * w1.z + b1.z, o1w = (c.w - mu) * r * w1.w + b1.w;
    __nv_bfloat162 p0 = __floats2bfloat162_rn(o0x, o0y);
    __nv_bfloat162 p1 = __floats2bfloat162_rn(o0z, o0w);
    __nv_bfloat162 p2 = __floats2bfloat162_rn(o1x, o1y);
    __nv_bfloat162 p3 = __floats2bfloat162_rn(o1z, o1w);
    uint4 u = make_uint4(*(uint32_t*)&p0, *(uint32_t*)&p1, *(uint32_t*)&p2, *(uint32_t*)&p3);
    *(uint4*)(g_xnb + (size_t)warp * DD + lane * 8) = u;
}

// ---------------- CSR build ----------------
__global__ void csr_zero() { if (threadIdx.x < NN) g_deg[threadIdx.x] = 0; }

__global__ void csr_hist(const int* __restrict__ ei32) {
    int e = blockIdx.x * blockDim.x + threadIdx.x;
    if (e < EE) atomicAdd(&g_deg[edge_val(ei32, 0, e)], 1);
}

__global__ void csr_scan() {
    __shared__ int s[NN];
    int t = threadIdx.x;
    s[t] = g_deg[t];
    __syncthreads();
    for (int o = 1; o < NN; o <<= 1) {
        int v = (t >= o) ? s[t - o] : 0;
        __syncthreads();
        s[t] += v;
        __syncthreads();
    }
    g_off[t + 1] = s[t];
    if (t == 0) g_off[0] = 0;
}

__global__ void csr_scatter(const int* __restrict__ ei32) {
    int e = blockIdx.x * blockDim.x + threadIdx.x;
    if (e >= EE) return;
    int src = edge_val(ei32, 0, e);
    int cnt = 0;
    for (int j = 0; j < e; j++) cnt += (edge_val(ei32, 0, j) == src);
    g_adj[g_off[src] + cnt] = edge_val(ei32, 1, e);
}

// ---------------- bf16 tensor-core GEMM, cp.async double-buffered ------------
// C[M, n0..n0+128) = A[M,256] @ Wt[n][k] + bias; CTA 128x128; 8 warps 4Mx2N,
// warp 32x64, mma m16n8k16. Outputs dispatched per 256-wide region (q/k/v).
__global__ __launch_bounds__(256) void gemm_bf16(const __nv_bfloat16* __restrict__ A,
                                                 const __nv_bfloat16* __restrict__ Wt,
                                                 const float* __restrict__ b0,
                                                 const float* __restrict__ b1,
                                                 const float* __restrict__ b2,
                                                 float* __restrict__ c0,
                                                 float* __restrict__ c1,
                                                 float* __restrict__ c2,
                                                 const float* __restrict__ resid,
                                                 const float* __restrict__ mask) {
    __shared__ __align__(16) __nv_bfloat16 As[2][128 * RS];
    __shared__ __align__(16) __nv_bfloat16 Ws[2][128 * RS];

    int tid = threadIdx.x;
    int wid = tid >> 5, lane = tid & 31;
    int m0 = blockIdx.y * 128, n0 = blockIdx.x * 128;
    int region = n0 >> 8;
    int nb0 = n0 & 255;
    float* C = (region == 0) ? c0 : (region == 1) ? c1 : c2;
    const float* bias = (region == 0) ? b0 : (region == 1) ? b1 : b2;

    int wm = (wid & 3) * 32, wn = (wid >> 2) * 64;
    int grp = lane >> 3, lrow = lane & 7;
    int rowA  = ((grp & 1) << 3) + lrow;
    int koffA = (grp >> 1) << 4;          // bytes
    int rowB  = ((grp >> 1) << 3) + lrow;
    int koffB = (grp & 1) << 4;

    uint32_t asb = (uint32_t)__cvta_generic_to_shared(&As[0][0]);
    uint32_t wsb = (uint32_t)__cvta_generic_to_shared(&Ws[0][0]);
    const int BUFB = 128 * RS * 2;        // bytes per buffer

    int sr = tid >> 2, sseg = tid & 3;    // staging: 2 passes of 64 rows x 4 segs

    float acc[2][8][4];
    #pragma unroll
    for (int mt = 0; mt < 2; mt++)
        #pragma unroll
        for (int nt = 0; nt < 8; nt++)
            #pragma unroll
            for (int v = 0; v < 4; v++) acc[mt][nt][v] = 0.0f;

    // prologue: stage chunk 0 into buf 0
    #pragma unroll
    for (int i = 0; i < 2; i++) {
        int r = sr + i * 64;
        CP16(asb + r * 80 + sseg * 16, A + (size_t)(m0 + r) * DD + sseg * 8);
        CP16(wsb + r * 80 + sseg * 16, Wt + (size_t)(n0 + r) * DD + sseg * 8);
    }
    CP_COMMIT();

    for (int c = 0; c < 8; c++) {
        CP_WAIT0();
        __syncthreads();
        if (c < 7) {
            int nb = (c + 1) & 1;
            #pragma unroll
            for (int i = 0; i < 2; i++) {
                int r = sr + i * 64;
                CP16(asb + nb * BUFB + r * 80 + sseg * 16,
                     A + (size_t)(m0 + r) * DD + (c + 1) * 32 + sseg * 8);
                CP16(wsb + nb * BUFB + r * 80 + sseg * 16,
                     Wt + (size_t)(n0 + r) * DD + (c + 1) * 32 + sseg * 8);
            }
            CP_COMMIT();
        }
        int cb = (c & 1) * BUFB;
        #pragma unroll
        for (int ks = 0; ks < 2; ks++) {
            uint32_t af[2][4], bf[4][4];
            ldsm4(af[0], asb + cb + (wm + rowA) * 80 + ks * 32 + koffA);
            ldsm4(af[1], asb + cb + (wm + 16 + rowA) * 80 + ks * 32 + koffA);
            #pragma unroll
            for (int g2 = 0; g2 < 4; g2++)
                ldsm4(bf[g2], wsb + cb + (wn + g2 * 16 + rowB) * 80 + ks * 32 + koffB);
            #pragma unroll
            for (int mt = 0; mt < 2; mt++)
                #pragma unroll
                for (int nt = 0; nt < 8; nt++)
                    mma_bf16(acc[mt][nt], af[mt], &bf[nt >> 1][(nt & 1) * 2]);
        }
        __syncthreads();
    }

    // epilogue: acc fragment c0=(g,2t) c1=(g,2t+1) c2=(g+8,2t) c3=(g+8,2t+1)
    int g = lane >> 2, t2 = (lane & 3) * 2;
    #pragma unroll
    for (int mt = 0; mt < 2; mt++) {
        #pragma unroll
        for (int half = 0; half < 2; half++) {
            int m = m0 + wm + mt * 16 + g + half * 8;
            float mk = resid ? mask[m] : 0.0f;
            #pragma unroll
            for (int nt = 0; nt < 8; nt++) {
                int n = nb0 + wn + nt * 8 + t2;
                float2 bb = *(const float2*)(bias + n);
                float cx = acc[mt][nt][half * 2 + 0] + bb.x;
                float cy = acc[mt][nt][half * 2 + 1] + bb.y;
                if (resid) {
                    float2 rv = *(const float2*)(resid + (size_t)m * DD + n);
                    cx = (cx + rv.x) * mk;
                    cy = (cy + rv.y) * mk;
                }
                *(float2*)(C + (size_t)m * DD + n) = make_float2(cx, cy);
            }
        }
    }
}

// ---------------- per-edge score+softmax, templated on #k-tiles ----------------
template <int NJ>
__device__ __forceinline__ void edge_compute(const float* __restrict__ Qs,
                                             const float* __restrict__ Ks,
                                             const float* __restrict__ kmS,
                                             float* __restrict__ Sc,
                                             int qg, int kg, unsigned gm) {
    float sc[4][NJ];
    #pragma unroll
    for (int i = 0; i < 4; i++)
        #pragma unroll
        for (int j = 0; j < NJ; j++) sc[i][j] = 0.0f;

    #pragma unroll
    for (int d = 0; d < 64; d += 4) {
        float4 qv[4], kv[NJ];
        #pragma unroll
        for (int i = 0; i < 4; i++) qv[i] = *(const float4*)&Qs[(qg * 4 + i) * 68 + d];
        #pragma unroll
        for (int j = 0; j < NJ; j++) kv[j] = *(const float4*)&Ks[(j * 8 + kg) * 68 + d];
        #pragma unroll
        for (int i = 0; i < 4; i++)
            #pragma unroll
            for (int j = 0; j < NJ; j++) {
                sc[i][j] = fmaf(qv[i].x, kv[j].x, sc[i][j]);
                sc[i][j] = fmaf(qv[i].y, kv[j].y, sc[i][j]);
                sc[i][j] = fmaf(qv[i].z, kv[j].z, sc[i][j]);
                sc[i][j] = fmaf(qv[i].w, kv[j].w, sc[i][j]);
            }
    }
    float mx[4] = {-1e30f, -1e30f, -1e30f, -1e30f};
    #pragma unroll
    for (int i = 0; i < 4; i++)
        #pragma unroll
        for (int j = 0; j < NJ; j++) {
            float km = kmS[j * 8 + kg];
            float s = (km > 0.0f) ? sc[i][j] * 0.125f : -1e30f;
            sc[i][j] = s;
            mx[i] = fmaxf(mx[i], s);
        }
    #pragma unroll
    for (int i = 0; i < 4; i++) {
        mx[i] = fmaxf(mx[i], __shfl_xor_sync(gm, mx[i], 1));
        mx[i] = fmaxf(mx[i], __shfl_xor_sync(gm, mx[i], 2));
        mx[i] = fmaxf(mx[i], __shfl_xor_sync(gm, mx[i], 4));
    }
    float sum[4] = {0.0f, 0.0f, 0.0f, 0.0f};
    #pragma unroll
    for (int i = 0; i < 4; i++)
        #pragma unroll
        for (int j = 0; j < NJ; j++) {
            float p = __expf(sc[i][j] - mx[i]) * kmS[j * 8 + kg];
            sc[i][j] = p;
            sum[i] += p;
        }
    #pragma unroll
    for (int i = 0; i < 4; i++) {
        sum[i] += __shfl_xor_sync(gm, sum[i], 1);
        sum[i] += __shfl_xor_sync(gm, sum[i], 2);
        sum[i] += __shfl_xor_sync(gm, sum[i], 4);
        float inv = (sum[i] > 0.0f) ? (1.0f / sum[i]) : 0.0f;
        #pragma unroll
        for (int j = 0; j < NJ; j++)
            Sc[(qg * 4 + i) * 65 + j * 8 + kg] = sc[i][j] * inv;
    }
}

// ---------------- per-(src,head) edge attention with length bounds ----------
__global__ __launch_bounds__(128) void attn_kernel(const float* __restrict__ masks) {
    extern __shared__ __align__(16) float sm[];
    float* Qs  = sm;            // 64 x (stride 68)
    float* Ks  = sm + 4352;
    float* Vs  = sm + 8704;
    float* Sc  = sm + 13056;    // 64 x (stride 65)
    float* kmS = sm + 17216;

    int src = blockIdx.x >> 2;
    int h   = blockIdx.x & 3;
    int tid = threadIdx.x;
    int qg = tid >> 3;
    int kg = tid & 7;
    unsigned gm = 0xffu << (((tid & 31) >> 3) * 8);

    int q_len = g_len[src];
    bool qact = (qg * 4 < q_len);

    {
        int r = tid >> 1, cb = (tid & 1) * 32;
        const float* gq = g_q + ((size_t)src * SS + r) * DD + h * HDIM;
        #pragma unroll
        for (int c = 0; c < 8; c++)
            *(float4*)&Qs[r * 68 + cb + c * 4] = *(const float4*)(gq + cb + c * 4);
    }
    float acc[4][8];
    #pragma unroll
    for (int i = 0; i < 4; i++)
        #pragma unroll
        for (int j = 0; j < 8; j++) acc[i][j] = 0.0f;

    int e0 = g_off[src], e1 = g_off[src + 1];
    __syncthreads();

    for (int e = e0; e < e1; e++) {
        int dst = g_adj[e];
        int k_len = g_len[dst];
        int nt8 = (k_len + 7) >> 3;
        int kup = nt8 << 3;
        int nc  = (kup + 15) >> 4;
        int rup = nc << 4;

        {
            int r = tid >> 1, cb = (tid & 1) * 32;
            if (r < rup) {
                const float* gk = g_k + ((size_t)dst * SS + r) * DD + h * HDIM;
                const float* gv = g_v + ((size_t)dst * SS + r) * DD + h * HDIM;
                #pragma unroll
                for (int c = 0; c < 8; c++) {
                    *(float4*)&Ks[r * 68 + cb + c * 4] = *(const float4*)(gk + cb + c * 4);
                    *(float4*)&Vs[r * 68 + cb + c * 4] = *(const float4*)(gv + cb + c * 4);
                }
            }
            if (tid < SS) kmS[tid] = masks[dst * SS + tid];
        }
        __syncthreads();

        if (qact) {
            switch (nc) {
                case 1:  edge_compute<2>(Qs, Ks, kmS, Sc, qg, kg, gm); break;
                case 2:  edge_compute<4>(Qs, Ks, kmS, Sc, qg, kg, gm); break;
                case 3:  edge_compute<6>(Qs, Ks, kmS, Sc, qg, kg, gm); break;
                default: edge_compute<8>(Qs, Ks, kmS, Sc, qg, kg, gm); break;
            }
        }
        __syncthreads();

        if (qact) {
            #pragma unroll 8
            for (int k = 0; k < kup; k++) {
                float a0 = Sc[(qg * 4 + 0) * 65 + k];
                float a1 = Sc[(qg * 4 + 1) * 65 + k];
                float a2 = Sc[(qg * 4 + 2) * 65 + k];
                float a3 = Sc[(qg * 4 + 3) * 65 + k];
                float4 v0 = *(float4*)&Vs[k * 68 + kg * 8];
                float4 v1 = *(float4*)&Vs[k * 68 + kg * 8 + 4];
                float vv[8] = {v0.x, v0.y, v0.z, v0.w, v1.x, v1.y, v1.z, v1.w};
                #pragma unroll
                for (int j = 0; j < 8; j++) {
                    acc[0][j] = fmaf(a0, vv[j], acc[0][j]);
                    acc[1][j] = fmaf(a1, vv[j], acc[1][j]);
                    acc[2][j] = fmaf(a2, vv[j], acc[2][j]);
                    acc[3][j] = fmaf(a3, vv[j], acc[3][j]);
                }
            }
        }
        __syncthreads();
    }

    // write context in bf16 (out-proj is the only consumer)
    #pragma unroll
    for (int i = 0; i < 4; i++) {
        int q = qg * 4 + i;
        __nv_bfloat16* o = g_ctxb + ((size_t)src * SS + q) * DD + h * HDIM + kg * 8;
        __nv_bfloat162 p0 = __floats2bfloat162_rn(acc[i][0], acc[i][1]);
        __nv_bfloat162 p1 = __floats2bfloat162_rn(acc[i][2], acc[i][3]);
        __nv_bfloat162 p2 = __floats2bfloat162_rn(acc[i][4], acc[i][5]);
        __nv_bfloat162 p3 = __floats2bfloat162_rn(acc[i][6], acc[i][7]);
        uint4 u = make_uint4(*(uint32_t*)&p0, *(uint32_t*)&p1,
                             *(uint32_t*)&p2, *(uint32_t*)&p3);
        *(uint4*)o = u;
    }
}

// ---------------- launcher ----------------
extern "C" void kernel_launch(void* const* d_in, const int* in_sizes, int n_in,
                              void* d_out, int out_size) {
    const float* nf = (const float*)d_in[0];
    const float* nm = (const float*)d_in[1];
    const float* lw = (const float*)d_in[2];
    const float* lb = (const float*)d_in[3];
    const float* wq = (const float*)d_in[4];
    const float* bq = (const float*)d_in[5];
    const float* wk = (const float*)d_in[6];
    const float* bk = (const float*)d_in[7];
    const float* wv = (const float*)d_in[8];
    const float* bv = (const float*)d_in[9];
    const float* wo = (const float*)d_in[10];
    const float* bo = (const float*)d_in[11];
    const int* ei32 = (const int*)d_in[13];
    float* out = (float*)d_out;

    __nv_bfloat16* p_xnb;  cudaGetSymbolAddress((void**)&p_xnb,  g_xnb);
    __nv_bfloat16* p_ctxb; cudaGetSymbolAddress((void**)&p_ctxb, g_ctxb);
    __nv_bfloat16* p_wtb;  cudaGetSymbolAddress((void**)&p_wtb,  g_wtb);
    float* p_q;   cudaGetSymbolAddress((void**)&p_q,   g_q);
    float* p_k;   cudaGetSymbolAddress((void**)&p_k,   g_k);
    float* p_v;   cudaGetSymbolAddress((void**)&p_v,   g_v);

    // launch order arranged so the 6th launch (ncu -s 5 -c 1) = fused QKV GEMM
    wtb_kernel<<<1024, 256>>>(wq, wk, wv, wo);                   // 1
    ln_kernel<<<MROWS / 8, 256>>>(nf, lw, lb);                   // 2
    detect_kernel<<<1, 256>>>(ei32);                             // 3
    len_kernel<<<4, 256>>>(nm);                                  // 4
    csr_zero<<<1, 1024>>>();                                     // 5

    dim3 gqkv(6, 512);                                           // 6 (profiled)
    gemm_bf16<<<gqkv, 256>>>(p_xnb, p_wtb, bq, bk, bv, p_q, p_k, p_v,
                             nullptr, nullptr);

    csr_hist<<<EE / 256, 256>>>(ei32);                           // 7
    csr_scan<<<1, 1024>>>();                                     // 8
    csr_scatter<<<EE / 256, 256>>>(ei32);                        // 9

    static const int ATTN_SMEM = 17280 * 4;                      // 10
    cudaFuncSetAttribute(attn_kernel, cudaFuncAttributeMaxDynamicSharedMemorySize, ATTN_SMEM);
    attn_kernel<<<NN * HH, 128, ATTN_SMEM>>>(nm);

    dim3 go(2, 512);                                             // 11
    gemm_bf16<<<go, 256>>>(p_ctxb, p_wtb + 768 * DD, bo, bo, bo,
                           out, out, out, nf, nm);
}

// round 6
// speedup vs baseline: 4.4397x; 1.9128x over previous
#include <cuda_runtime.h>
#include <cuda_bf16.h>
#include <cstdint>

// Problem constants (fixed by the reference)
#define NN 1024
#define SS 64
#define DD 256
#define HH 4
#define HDIM 64
#define EE 4096
#define MROWS (NN * SS)   // 65536

// ---------------- scratch (device globals; no allocs allowed) ----------------
__device__ __nv_bfloat16 g_xnb[MROWS * DD];     // layernormed features (bf16)
__device__ __nv_bfloat16 g_qkvb[MROWS * 768];   // stacked q|k|v (bf16)
__device__ __nv_bfloat16 g_ctxb[MROWS * DD];    // per-src summed context (bf16)
__device__ __nv_bfloat16 g_wtb[4 * DD * DD];    // stacked weights [n][k]: wq,wk,wv,wo
__device__ float g_bqkv[768];                   // stacked biases bq|bk|bv
__device__ int g_deg[NN];
__device__ int g_off[NN + 1];
__device__ int g_adj[EE];
__device__ int g_len[NN];
__device__ int g_step;

// ---------------- mma helpers ----------------
__device__ __forceinline__ void ldsm4(uint32_t* r, uint32_t addr) {
    asm volatile("ldmatrix.sync.aligned.m8n8.x4.shared.b16 {%0,%1,%2,%3}, [%4];\n"
                 : "=r"(r[0]), "=r"(r[1]), "=r"(r[2]), "=r"(r[3]) : "r"(addr));
}

__device__ __forceinline__ void ldsm4t(uint32_t* r, uint32_t addr) {
    asm volatile("ldmatrix.sync.aligned.m8n8.x4.trans.shared.b16 {%0,%1,%2,%3}, [%4];\n"
                 : "=r"(r[0]), "=r"(r[1]), "=r"(r[2]), "=r"(r[3]) : "r"(addr));
}

__device__ __forceinline__ void mma_bf16(float* d, const uint32_t* a, const uint32_t* b) {
    asm volatile(
        "mma.sync.aligned.m16n8k16.row.col.f32.bf16.bf16.f32 "
        "{%0,%1,%2,%3}, {%4,%5,%6,%7}, {%8,%9}, {%0,%1,%2,%3};\n"
        : "+f"(d[0]), "+f"(d[1]), "+f"(d[2]), "+f"(d[3])
        : "r"(a[0]), "r"(a[1]), "r"(a[2]), "r"(a[3]), "r"(b[0]), "r"(b[1]));
}

__device__ __forceinline__ uint32_t packbf(float x, float y) {
    __nv_bfloat162 p = __floats2bfloat162_rn(x, y);
    return *(uint32_t*)&p;
}

#define CP16(dst, src) \
    asm volatile("cp.async.cg.shared.global [%0], [%1], 16;\n" :: "r"(dst), "l"(src))
#define CP_COMMIT() asm volatile("cp.async.commit_group;\n" ::: "memory")
#define CP_WAIT0()  asm volatile("cp.async.wait_group 0;\n" ::: "memory")

// ---------------- edge dtype detection ----------------
__global__ void detect_kernel(const int* __restrict__ ei32) {
    int nz = 0;
    for (int i = threadIdx.x; i < EE; i += blockDim.x)
        nz |= (ei32[2 * i + 1] != 0);
    nz = __syncthreads_or(nz);
    if (threadIdx.x == 0) g_step = nz ? 1 : 2;
}

__device__ __forceinline__ int edge_val(const int* __restrict__ ei32, int row, int e) {
    return ei32[g_step * (row * EE + e)];
}

// ---------------- weights: stacked transpose + bf16: wtb[n][k] ----------------
__global__ void wtb_kernel(const float* __restrict__ wq, const float* __restrict__ wk,
                           const float* __restrict__ wv, const float* __restrict__ wo) {
    int bx = blockIdx.x;  // 0..1023
    const float* w = (bx < 256) ? wq : (bx < 512) ? wk : (bx < 768) ? wv : wo;
    int n = bx & 255;
    for (int k = threadIdx.x; k < DD; k += blockDim.x)
        g_wtb[bx * DD + k] = __float2bfloat16(w[k * DD + n]);
}

__global__ void bias_kernel(const float* __restrict__ bq, const float* __restrict__ bk,
                            const float* __restrict__ bv) {
    int i = blockIdx.x * 256 + threadIdx.x;  // 0..767
    g_bqkv[i] = (i < 256) ? bq[i] : (i < 512) ? bk[i - 256] : bv[i - 512];
}

// ---------------- lengths: warp per node ----------------
__global__ void len_kernel(const float* __restrict__ masks) {
    int w = (blockIdx.x * blockDim.x + threadIdx.x) >> 5;
    int lane = threadIdx.x & 31;
    if (w >= NN) return;
    int a = masks[w * SS + lane] > 0.0f;
    int b = masks[w * SS + 32 + lane] > 0.0f;
    int c = __popc(__ballot_sync(0xffffffffu, a)) + __popc(__ballot_sync(0xffffffffu, b));
    if (lane == 0) g_len[w] = c;
}

// ---------------- LayerNorm -> bf16 output ----------------
__global__ __launch_bounds__(256) void ln_kernel(const float* __restrict__ x,
                                                 const float* __restrict__ w,
                                                 const float* __restrict__ b) {
    int warp = (blockIdx.x * blockDim.x + threadIdx.x) >> 5;
    int lane = threadIdx.x & 31;
    if (warp >= MROWS) return;
    const float* xr = x + (size_t)warp * DD + lane * 8;
    float4 a = *(const float4*)xr;
    float4 c = *(const float4*)(xr + 4);
    float s  = a.x + a.y + a.z + a.w + c.x + c.y + c.z + c.w;
    float s2 = a.x*a.x + a.y*a.y + a.z*a.z + a.w*a.w
             + c.x*c.x + c.y*c.y + c.z*c.z + c.w*c.w;
    #pragma unroll
    for (int o = 16; o > 0; o >>= 1) {
        s  += __shfl_xor_sync(0xffffffffu, s,  o);
        s2 += __shfl_xor_sync(0xffffffffu, s2, o);
    }
    float mu  = s * (1.0f / DD);
    float var = s2 * (1.0f / DD) - mu * mu;
    float r = rsqrtf(var + 1e-5f);
    float4 w0 = *(const float4*)(w + lane * 8);
    float4 w1 = *(const float4*)(w + lane * 8 + 4);
    float4 b0 = *(const float4*)(b + lane * 8);
    float4 b1 = *(const float4*)(b + lane * 8 + 4);
    float o0x = (a.x - mu) * r * w0.x + b0.x, o0y = (a.y - mu) * r * w0.y + b0.y;
    float o0z = (a.z - mu) * r * w0.z + b0.z, o0w = (a.w - mu) * r * w0.w + b0.w;
    float o1x = (c.x - mu) * r * w1.x + b1.x, o1y = (c.y - mu) * r * w1.y + b1.y;
    float o1z = (c.z - mu) * r * w1.z + b1.z, o1w = (c.w - mu) * r * w1.w + b1.w;
    uint4 u = make_uint4(packbf(o0x, o0y), packbf(o0z, o0w),
                         packbf(o1x, o1y), packbf(o1z, o1w));
    *(uint4*)(g_xnb + (size_t)warp * DD + lane * 8) = u;
}

// ---------------- CSR build ----------------
__global__ void csr_zero() { if (threadIdx.x < NN) g_deg[threadIdx.x] = 0; }

__global__ void csr_hist(const int* __restrict__ ei32) {
    int e = blockIdx.x * blockDim.x + threadIdx.x;
    if (e < EE) atomicAdd(&g_deg[edge_val(ei32, 0, e)], 1);
}

__global__ void csr_scan() {
    __shared__ int s[NN];
    int t = threadIdx.x;
    s[t] = g_deg[t];
    __syncthreads();
    for (int o = 1; o < NN; o <<= 1) {
        int v = (t >= o) ? s[t - o] : 0;
        __syncthreads();
        s[t] += v;
        __syncthreads();
    }
    g_off[t + 1] = s[t];
    if (t == 0) g_off[0] = 0;
}

__global__ void csr_scatter(const int* __restrict__ ei32) {
    int e = blockIdx.x * blockDim.x + threadIdx.x;
    if (e >= EE) return;
    int src = edge_val(ei32, 0, e);
    int cnt = 0;
    for (int j = 0; j < e; j++) cnt += (edge_val(ei32, 0, j) == src);
    g_adj[g_off[src] + cnt] = edge_val(ei32, 1, e);
}

// ---------------- full-K single-stage bf16 GEMM ----------------
// CTA tile 128m x 64n, K=256 staged entirely (one cp.async batch, one sync).
// 8 warps: 4M x 2N, warp 32x32, mma m16n8k16, 16 straight-line k-steps.
// Output: bf16 (Cb, stride ldc) or fp32 (Cf, +resid*mask), per launch.
__global__ __launch_bounds__(256) void gemm2(const __nv_bfloat16* __restrict__ A,
                                             const __nv_bfloat16* __restrict__ Wt,
                                             const float* __restrict__ bias,
                                             __nv_bfloat16* __restrict__ Cb, int ldc,
                                             float* __restrict__ Cf,
                                             const float* __restrict__ resid,
                                             const float* __restrict__ mask) {
    extern __shared__ __align__(16) __nv_bfloat16 smem2[];
    __nv_bfloat16* As = smem2;              // [128][264] (stride 528 B)
    __nv_bfloat16* Ws = smem2 + 128 * 264;  // [64][264]

    int tid = threadIdx.x;
    int wid = tid >> 5, lane = tid & 31;
    int m0 = blockIdx.y * 128, n0 = blockIdx.x * 64;
    int wm = (wid & 3) * 32, wn = (wid >> 2) * 32;

    uint32_t asb = (uint32_t)__cvta_generic_to_shared(As);
    uint32_t wsb = (uint32_t)__cvta_generic_to_shared(Ws);

    // stage the whole K range
    #pragma unroll
    for (int i = 0; i < 16; i++) {
        int t = tid + i * 256;               // 4096 chunks: 128 rows x 32
        int r = t >> 5, c = t & 31;
        CP16(asb + r * 528 + c * 16, A + (size_t)(m0 + r) * DD + c * 8);
    }
    #pragma unroll
    for (int i = 0; i < 8; i++) {
        int t = tid + i * 256;               // 2048 chunks: 64 rows x 32
        int r = t >> 5, c = t & 31;
        CP16(wsb + r * 528 + c * 16, Wt + (size_t)(n0 + r) * DD + c * 8);
    }
    CP_COMMIT();

    int grp = lane >> 3, lrow = lane & 7;
    int rowA  = ((grp & 1) << 3) + lrow;
    int koffA = (grp >> 1) << 4;
    int rowB  = ((grp >> 1) << 3) + lrow;
    int koffB = (grp & 1) << 4;

    float acc[2][4][4];
    #pragma unroll
    for (int mt = 0; mt < 2; mt++)
        #pragma unroll
        for (int nt = 0; nt < 4; nt++)
            #pragma unroll
            for (int v = 0; v < 4; v++) acc[mt][nt][v] = 0.0f;

    CP_WAIT0();
    __syncthreads();

    #pragma unroll
    for (int kk = 0; kk < 16; kk++) {
        uint32_t af[2][4], b0[4], b1[4];
        ldsm4(af[0], asb + (wm + rowA) * 528 + kk * 32 + koffA);
        ldsm4(af[1], asb + (wm + 16 + rowA) * 528 + kk * 32 + koffA);
        ldsm4(b0, wsb + (wn + rowB) * 528 + kk * 32 + koffB);
        ldsm4(b1, wsb + (wn + 16 + rowB) * 528 + kk * 32 + koffB);
        #pragma unroll
        for (int mt = 0; mt < 2; mt++) {
            mma_bf16(acc[mt][0], af[mt], &b0[0]);
            mma_bf16(acc[mt][1], af[mt], &b0[2]);
            mma_bf16(acc[mt][2], af[mt], &b1[0]);
            mma_bf16(acc[mt][3], af[mt], &b1[2]);
        }
    }

    int g = lane >> 2, t2 = (lane & 3) * 2;
    #pragma unroll
    for (int mt = 0; mt < 2; mt++) {
        #pragma unroll
        for (int half = 0; half < 2; half++) {
            int m = m0 + wm + mt * 16 + g + half * 8;
            if (Cf) {
                float mk = mask[m];
                #pragma unroll
                for (int nt = 0; nt < 4; nt++) {
                    int n = n0 + wn + nt * 8 + t2;
                    float2 bb = *(const float2*)(bias + n);
                    float2 rv = *(const float2*)(resid + (size_t)m * DD + n);
                    float cx = (acc[mt][nt][half * 2 + 0] + bb.x + rv.x) * mk;
                    float cy = (acc[mt][nt][half * 2 + 1] + bb.y + rv.y) * mk;
                    *(float2*)(Cf + (size_t)m * DD + n) = make_float2(cx, cy);
                }
            } else {
                #pragma unroll
                for (int nt = 0; nt < 4; nt++) {
                    int n = n0 + wn + nt * 8 + t2;
                    float2 bb = *(const float2*)(bias + n);
                    uint32_t p = packbf(acc[mt][nt][half * 2 + 0] + bb.x,
                                        acc[mt][nt][half * 2 + 1] + bb.y);
                    *(uint32_t*)(Cb + (size_t)m * ldc + n) = p;
                }
            }
        }
    }
}

// ---------------- per-edge score+softmax+PV, tensor cores ----------------
// NKB = ceil(k_len/16), 1..4. S frags in registers, softmax in registers
// (quad shuffles), P packed to bf16 A-frags, PV via ldmatrix.trans on V.
template <int NKB>
__device__ __forceinline__ void attn_edge(uint32_t ksb, uint32_t vsb,
                                          const uint32_t (&qf)[4][4],
                                          float (&acc)[8][4],
                                          int k_len, int lane) {
    int grp = lane >> 3, lrow = lane & 7;
    int rowB  = ((grp >> 1) << 3) + lrow;
    int koffB = (grp & 1) << 4;

    float sc[2 * NKB][4];
    #pragma unroll
    for (int nt = 0; nt < 2 * NKB; nt++)
        #pragma unroll
        for (int v = 0; v < 4; v++) sc[nt][v] = 0.0f;

    #pragma unroll
    for (int ds = 0; ds < 4; ds++) {
        #pragma unroll
        for (int g2 = 0; g2 < NKB; g2++) {
            uint32_t bf[4];
            ldsm4(bf, ksb + (g2 * 16 + rowB) * 144 + ds * 32 + koffB);
            mma_bf16(sc[2 * g2],     qf[ds], &bf[0]);
            mma_bf16(sc[2 * g2 + 1], qf[ds], &bf[2]);
        }
    }

    // mask (prefix: col < k_len), scale, row max over quad
    int cb = 2 * (lane & 3);
    float m1 = -1e30f, m2 = -1e30f;
    #pragma unroll
    for (int nt = 0; nt < 2 * NKB; nt++) {
        int c0 = nt * 8 + cb;
        bool v0 = c0 < k_len, v1 = (c0 + 1) < k_len;
        sc[nt][0] = v0 ? sc[nt][0] * 0.125f : -1e30f;
        sc[nt][1] = v1 ? sc[nt][1] * 0.125f : -1e30f;
        sc[nt][2] = v0 ? sc[nt][2] * 0.125f : -1e30f;
        sc[nt][3] = v1 ? sc[nt][3] * 0.125f : -1e30f;
        m1 = fmaxf(m1, fmaxf(sc[nt][0], sc[nt][1]));
        m2 = fmaxf(m2, fmaxf(sc[nt][2], sc[nt][3]));
    }
    m1 = fmaxf(m1, __shfl_xor_sync(0xffffffffu, m1, 1));
    m1 = fmaxf(m1, __shfl_xor_sync(0xffffffffu, m1, 2));
    m2 = fmaxf(m2, __shfl_xor_sync(0xffffffffu, m2, 1));
    m2 = fmaxf(m2, __shfl_xor_sync(0xffffffffu, m2, 2));

    float s1 = 0.0f, s2 = 0.0f;
    #pragma unroll
    for (int nt = 0; nt < 2 * NKB; nt++) {
        if (nt * 8 < k_len) {                 // uniform branch; skip dead tiles
            sc[nt][0] = __expf(sc[nt][0] - m1);
            sc[nt][1] = __expf(sc[nt][1] - m1);
            sc[nt][2] = __expf(sc[nt][2] - m2);
            sc[nt][3] = __expf(sc[nt][3] - m2);
        } else {
            sc[nt][0] = sc[nt][1] = sc[nt][2] = sc[nt][3] = 0.0f;
        }
        s1 += sc[nt][0] + sc[nt][1];
        s2 += sc[nt][2] + sc[nt][3];
    }
    s1 += __shfl_xor_sync(0xffffffffu, s1, 1);
    s1 += __shfl_xor_sync(0xffffffffu, s1, 2);
    s2 += __shfl_xor_sync(0xffffffffu, s2, 1);
    s2 += __shfl_xor_sync(0xffffffffu, s2, 2);
    float i1 = 1.0f / s1, i2 = 1.0f / s2;     // k_len >= 1 -> s > 0

    // PV: P(bf16 A-frags from S-frags) x V^T (ldmatrix.trans)
    #pragma unroll
    for (int kb = 0; kb < NKB; kb++) {
        uint32_t pr[4];
        pr[0] = packbf(sc[2 * kb][0] * i1,     sc[2 * kb][1] * i1);
        pr[1] = packbf(sc[2 * kb][2] * i2,     sc[2 * kb][3] * i2);
        pr[2] = packbf(sc[2 * kb + 1][0] * i1, sc[2 * kb + 1][1] * i1);
        pr[3] = packbf(sc[2 * kb + 1][2] * i2, sc[2 * kb + 1][3] * i2);
        #pragma unroll
        for (int dg = 0; dg < 4; dg++) {
            uint32_t vb[4];
            ldsm4t(vb, vsb + (kb * 16 + ((grp & 1) << 3) + lrow) * 144
                          + dg * 32 + ((grp >> 1) << 4));
            mma_bf16(acc[dg * 2],     pr, &vb[0]);
            mma_bf16(acc[dg * 2 + 1], pr, &vb[2]);
        }
    }
}

// ---------------- per-(src,head) edge attention, tensor cores ---------------
__global__ __launch_bounds__(128) void attn2(const __nv_bfloat16* __restrict__ qkv) {
    __shared__ __align__(16) __nv_bfloat16 Qs[64 * 72];
    __shared__ __align__(16) __nv_bfloat16 Ks[64 * 72];
    __shared__ __align__(16) __nv_bfloat16 Vs[64 * 72];

    int src = blockIdx.x >> 2;
    int h   = blockIdx.x & 3;
    int tid = threadIdx.x;
    int w = tid >> 5, lane = tid & 31;

    // load Q tile [64 x 64] bf16
    #pragma unroll
    for (int i = 0; i < 4; i++) {
        int t = tid + i * 128;
        int r = t >> 3, c = t & 7;
        *(uint4*)&Qs[r * 72 + c * 8] =
            *(const uint4*)(qkv + (size_t)(src * SS + r) * 768 + h * HDIM + c * 8);
    }
    __syncthreads();

    uint32_t qsb = (uint32_t)__cvta_generic_to_shared(Qs);
    uint32_t ksb = (uint32_t)__cvta_generic_to_shared(Ks);
    uint32_t vsb = (uint32_t)__cvta_generic_to_shared(Vs);

    int grp = lane >> 3, lrow = lane & 7;
    int rowA  = ((grp & 1) << 3) + lrow;
    int koffA = (grp >> 1) << 4;

    uint32_t qf[4][4];
    #pragma unroll
    for (int ds = 0; ds < 4; ds++)
        ldsm4(qf[ds], qsb + (16 * w + rowA) * 144 + ds * 32 + koffA);

    float acc[8][4];
    #pragma unroll
    for (int i = 0; i < 8; i++)
        #pragma unroll
        for (int v = 0; v < 4; v++) acc[i][v] = 0.0f;

    int q_len = g_len[src];
    bool act = (16 * w < q_len);
    int e0 = g_off[src], e1 = g_off[src + 1];

    for (int e = e0; e < e1; e++) {
        int dst = g_adj[e];
        int k_len = g_len[dst];
        int nkb = (k_len + 15) >> 4;          // 1..4
        int rup = nkb << 4;

        for (int t = tid; t < rup * 8; t += 128) {
            int r = t >> 3, c = t & 7;
            size_t base = (size_t)(dst * SS + r) * 768 + h * HDIM + c * 8;
            *(uint4*)&Ks[r * 72 + c * 8] = *(const uint4*)(qkv + base + 256);
            *(uint4*)&Vs[r * 72 + c * 8] = *(const uint4*)(qkv + base + 512);
        }
        __syncthreads();

        if (act) {
            switch (nkb) {
                case 1:  attn_edge<1>(ksb, vsb, qf, acc, k_len, lane); break;
                case 2:  attn_edge<2>(ksb, vsb, qf, acc, k_len, lane); break;
                case 3:  attn_edge<3>(ksb, vsb, qf, acc, k_len, lane); break;
                default: attn_edge<4>(ksb, vsb, qf, acc, k_len, lane); break;
            }
        }
        __syncthreads();
    }

    // write ctx (bf16), rows r1/r2 per fragment layout; inactive warps write 0
    int r1 = 16 * w + (lane >> 2);
    int t2 = 2 * (lane & 3);
    #pragma unroll
    for (int dt = 0; dt < 8; dt++) {
        size_t b1 = (size_t)(src * SS + r1) * DD + h * HDIM + dt * 8 + t2;
        size_t b2 = (size_t)(src * SS + r1 + 8) * DD + h * HDIM + dt * 8 + t2;
        *(uint32_t*)(g_ctxb + b1) = packbf(acc[dt][0], acc[dt][1]);
        *(uint32_t*)(g_ctxb + b2) = packbf(acc[dt][2], acc[dt][3]);
    }
}

// ---------------- launcher ----------------
extern "C" void kernel_launch(void* const* d_in, const int* in_sizes, int n_in,
                              void* d_out, int out_size) {
    const float* nf = (const float*)d_in[0];
    const float* nm = (const float*)d_in[1];
    const float* lw = (const float*)d_in[2];
    const float* lb = (const float*)d_in[3];
    const float* wq = (const float*)d_in[4];
    const float* bq = (const float*)d_in[5];
    const float* wk = (const float*)d_in[6];
    const float* bk = (const float*)d_in[7];
    const float* wv = (const float*)d_in[8];
    const float* bv = (const float*)d_in[9];
    const float* wo = (const float*)d_in[10];
    const float* bo = (const float*)d_in[11];
    const int* ei32 = (const int*)d_in[13];
    float* out = (float*)d_out;

    __nv_bfloat16 *p_xnb, *p_qkvb, *p_ctxb, *p_wtb;
    float* p_bqkv;
    cudaGetSymbolAddress((void**)&p_xnb,  g_xnb);
    cudaGetSymbolAddress((void**)&p_qkvb, g_qkvb);
    cudaGetSymbolAddress((void**)&p_ctxb, g_ctxb);
    cudaGetSymbolAddress((void**)&p_wtb,  g_wtb);
    cudaGetSymbolAddress((void**)&p_bqkv, g_bqkv);

    static const int GEMM_SMEM = (128 + 64) * 264 * 2;  // 101376 B
    cudaFuncSetAttribute(gemm2, cudaFuncAttributeMaxDynamicSharedMemorySize, GEMM_SMEM);

    wtb_kernel<<<1024, 256>>>(wq, wk, wv, wo);                       // 1
    bias_kernel<<<3, 256>>>(bq, bk, bv);                             // 2
    ln_kernel<<<MROWS / 8, 256>>>(nf, lw, lb);                       // 3

    dim3 gqkv(12, 512);                                              // 4: fused QKV
    gemm2<<<gqkv, 256, GEMM_SMEM>>>(p_xnb, p_wtb, p_bqkv,
                                    p_qkvb, 768, nullptr, nullptr, nullptr);

    detect_kernel<<<1, 256>>>(ei32);                                 // 5
    len_kernel<<<128, 256>>>(nm);                                    // 6
    csr_zero<<<1, 1024>>>();                                         // 7
    csr_hist<<<EE / 256, 256>>>(ei32);                               // 8
    csr_scan<<<1, 1024>>>();                                         // 9
    csr_scatter<<<EE / 256, 256>>>(ei32);                            // 10

    attn2<<<NN * HH, 128>>>(p_qkvb);                                 // 11

    dim3 go(4, 512);                                                 // 12: out-proj
    gemm2<<<go, 256, GEMM_SMEM>>>(p_ctxb, p_wtb + 768 * DD, bo,
                                  nullptr, 0, out, nf, nm);
}